// round 2
// baseline (speedup 1.0000x reference)
#include <cuda_runtime.h>
#include <math.h>
#include <stdint.h>

#define VERY_NEG (-1e30f)

// Problem constants (fixed shapes from reference)
constexpr int Bz = 128;
constexpr int S  = 256;
constexpr int H  = 256;
constexpr int NH = 8;
constexpr int Dh = 32;
constexpr int C  = 20000;
constexpr int A  = 8;
constexpr int BS = Bz * S;         // 32768
constexpr int CA = C * A;          // 160000
constexpr int FF = 4 * H;          // 1024

// ---------------- scratch (device globals: allocation-free contract) ----------
__device__ float g_xcat[(size_t)CA * 2 * H];  // [160000, 512] gathered (leaves*m | anc*m)
__device__ float g_hid [(size_t)CA * H];      // [160000, 256]
__device__ float g_s   [CA];                  // [160000]
__device__ float g_dag [(size_t)C * H];       // [20000, 256] dag embeddings
__device__ float g_xv  [(size_t)BS * H];      // visit embed
__device__ float g_xd  [(size_t)BS * H];      // dag embed
__device__ float g_t   [(size_t)BS * H];      // post-wo residual stream
__device__ float g_q   [(size_t)BS * H];
__device__ float g_k   [(size_t)BS * H];
__device__ float g_v   [(size_t)BS * H];
__device__ float g_ctx [(size_t)BS * H];
__device__ float g_ffn [(size_t)BS * FF];
__device__ float g_xdo [(size_t)BS * H];      // dag encoder output (pooled next)

// ---------------- generic 128x128x8 SGEMM, fused epilogue ---------------------
// C = [RELU]( A[M,K] @ B[K,N] + bias[N] ) + Res[M,N]
// Requires: M%128==0, N%128==0, K%8==0 (all shapes here satisfy this).
template <bool RELU, bool BIAS, bool RES>
__global__ __launch_bounds__(256)
void sgemm_kernel(const float* __restrict__ Am, const float* __restrict__ Bm,
                  const float* __restrict__ bias, const float* __restrict__ Res,
                  float* __restrict__ Cm, int M, int N, int K)
{
    __shared__ float As[8][128];
    __shared__ float Bs[8][128];
    const int tid = threadIdx.x;
    const int m0 = blockIdx.y * 128;
    const int n0 = blockIdx.x * 128;

    const int arow = tid >> 1;            // 0..127
    const int acol = (tid & 1) << 2;      // 0 or 4
    const int brow = tid >> 5;            // 0..7
    const int bcol = (tid & 31) << 2;     // 0..124

    const int rg = (tid >> 4) << 3;       // 0..120 step 8
    const int cg = (tid & 15) << 3;       // 0..120 step 8

    const float* Ap = Am + (size_t)(m0 + arow) * K + acol;
    const float* Bp = Bm + (size_t)brow * N + n0 + bcol;

    float acc[8][8];
    #pragma unroll
    for (int i = 0; i < 8; i++)
        #pragma unroll
        for (int j = 0; j < 8; j++) acc[i][j] = 0.f;

    for (int k0 = 0; k0 < K; k0 += 8) {
        float4 av = *(const float4*)Ap;
        float4 bv = *(const float4*)Bp;
        As[acol + 0][arow] = av.x;
        As[acol + 1][arow] = av.y;
        As[acol + 2][arow] = av.z;
        As[acol + 3][arow] = av.w;
        *(float4*)&Bs[brow][bcol] = bv;
        __syncthreads();
        #pragma unroll
        for (int kk = 0; kk < 8; kk++) {
            float a[8], b[8];
            #pragma unroll
            for (int i = 0; i < 8; i++) a[i] = As[kk][rg + i];
            #pragma unroll
            for (int j = 0; j < 8; j++) b[j] = Bs[kk][cg + j];
            #pragma unroll
            for (int i = 0; i < 8; i++)
                #pragma unroll
                for (int j = 0; j < 8; j++)
                    acc[i][j] = fmaf(a[i], b[j], acc[i][j]);
        }
        __syncthreads();
        Ap += 8;
        Bp += (size_t)8 * N;
    }

    #pragma unroll
    for (int i = 0; i < 8; i++) {
        const size_t base = (size_t)(m0 + rg + i) * N + n0 + cg;
        #pragma unroll
        for (int j4 = 0; j4 < 2; j4++) {
            float4 v;
            v.x = acc[i][j4 * 4 + 0];
            v.y = acc[i][j4 * 4 + 1];
            v.z = acc[i][j4 * 4 + 2];
            v.w = acc[i][j4 * 4 + 3];
            if (BIAS) {
                const float4 bb = *(const float4*)&bias[n0 + cg + j4 * 4];
                v.x += bb.x; v.y += bb.y; v.z += bb.z; v.w += bb.w;
            }
            if (RELU) {
                v.x = fmaxf(v.x, 0.f); v.y = fmaxf(v.y, 0.f);
                v.z = fmaxf(v.z, 0.f); v.w = fmaxf(v.w, 0.f);
            }
            if (RES) {
                const float4 rr = *(const float4*)&Res[base + j4 * 4];
                v.x += rr.x; v.y += rr.y; v.z += rr.z; v.w += rr.w;
            }
            *(float4*)&Cm[base + j4 * 4] = v;
        }
    }
}

// ---------------- DAG stage kernels -------------------------------------------
__global__ void gather_xcat_kernel(const int* __restrict__ leaves, const int* __restrict__ anc,
                                   const float* __restrict__ mask, const float* __restrict__ emb,
                                   float* __restrict__ xcat)
{
    int idx = blockIdx.x * blockDim.x + threadIdx.x;  // over CA*64 float4 slots
    if (idx >= CA * 64) return;
    int ca = idx >> 6;
    int h4 = (idx & 63) << 2;
    float m = mask[ca];
    int li = leaves[ca], ai = anc[ca];
    float4 lv = *(const float4*)&emb[(size_t)li * H + h4];
    float4 av = *(const float4*)&emb[(size_t)ai * H + h4];
    float4 l2 = make_float4(lv.x * m, lv.y * m, lv.z * m, lv.w * m);
    float4 a2 = make_float4(av.x * m, av.y * m, av.z * m, av.w * m);
    size_t rb = (size_t)ca * 512;
    *(float4*)&xcat[rb + h4] = l2;
    *(float4*)&xcat[rb + 256 + h4] = a2;
}

// s[row] = hid[row,:] . w2 + b2     (one warp per row)
__global__ void dag_score_kernel(const float* __restrict__ hid, const float* __restrict__ w2,
                                 const float* __restrict__ b2, float* __restrict__ s)
{
    int gw = (blockIdx.x * blockDim.x + threadIdx.x) >> 5;
    int lane = threadIdx.x & 31;
    if (gw >= CA) return;
    const float* hp = hid + (size_t)gw * H;
    float4 h0 = *(const float4*)&hp[lane * 4];
    float4 h1 = *(const float4*)&hp[128 + lane * 4];
    float4 w0 = *(const float4*)&w2[lane * 4];
    float4 w1 = *(const float4*)&w2[128 + lane * 4];
    float acc = h0.x * w0.x + h0.y * w0.y + h0.z * w0.z + h0.w * w0.w
              + h1.x * w1.x + h1.y * w1.y + h1.z * w1.z + h1.w * w1.w;
    #pragma unroll
    for (int off = 16; off; off >>= 1) acc += __shfl_xor_sync(0xffffffffu, acc, off);
    if (lane == 0) s[gw] = acc + b2[0];
}

// per code: softmax over A=8 (masked) then dag[c,:] = sum_a w[a] * (anc*m)[c,a,:]
__global__ void dag_softmax_kernel(const float* __restrict__ s, const float* __restrict__ mask,
                                   const float* __restrict__ xcat, float* __restrict__ dag)
{
    int gw = (blockIdx.x * blockDim.x + threadIdx.x) >> 5;  // one warp per code
    int lane = threadIdx.x & 31;
    if (gw >= C) return;
    float sv = -3.0e38f;
    if (lane < 8) {
        float m = mask[gw * 8 + lane];
        sv = s[gw * 8 + lane] + (1.f - m) * VERY_NEG;
    }
    float mx = sv;
    #pragma unroll
    for (int off = 4; off; off >>= 1) mx = fmaxf(mx, __shfl_xor_sync(0xffffffffu, mx, off));
    float e = (lane < 8) ? __expf(sv - mx) : 0.f;
    float su = e;
    #pragma unroll
    for (int off = 4; off; off >>= 1) su += __shfl_xor_sync(0xffffffffu, su, off);
    float wv = e / su;
    float w8[8];
    #pragma unroll
    for (int a = 0; a < 8; a++) w8[a] = __shfl_sync(0xffffffffu, wv, a);

    const float4* xc4 = (const float4*)xcat;
    const size_t rowbase = (size_t)gw * 8 * 128 + 64;  // anc half, in float4 units
    #pragma unroll
    for (int rep = 0; rep < 2; rep++) {
        int f4i = lane + rep * 32;  // 0..63
        float4 acc = make_float4(0.f, 0.f, 0.f, 0.f);
        #pragma unroll
        for (int a = 0; a < 8; a++) {
            float4 v = xc4[rowbase + (size_t)a * 128 + f4i];
            acc.x = fmaf(w8[a], v.x, acc.x);
            acc.y = fmaf(w8[a], v.y, acc.y);
            acc.z = fmaf(w8[a], v.z, acc.z);
            acc.w = fmaf(w8[a], v.w, acc.w);
        }
        ((float4*)dag)[(size_t)gw * 64 + f4i] = acc;
    }
}

// embed both streams: xv = embed_inputs[id]; xd = (id==0) ? 0 : dag[id-1]
__global__ void embed_gather_kernel(const int* __restrict__ ids, const float* __restrict__ embw,
                                    const float* __restrict__ dag, float* __restrict__ xv,
                                    float* __restrict__ xd)
{
    int idx = blockIdx.x * blockDim.x + threadIdx.x;  // BS*64
    if (idx >= BS * 64) return;
    int bs = idx >> 6, h4 = idx & 63;
    int id = ids[bs];
    ((float4*)xv)[(size_t)bs * 64 + h4] = ((const float4*)embw)[(size_t)id * 64 + h4];
    float4 dv = make_float4(0.f, 0.f, 0.f, 0.f);
    if (id > 0) dv = ((const float4*)dag)[(size_t)(id - 1) * 64 + h4];
    ((float4*)xd)[(size_t)bs * 64 + h4] = dv;
}

// ---------------- attention: one block per (b, head), one query per thread ----
__global__ void attention_kernel(const float* __restrict__ Q, const float* __restrict__ K,
                                 const float* __restrict__ V, const float* __restrict__ cmask,
                                 float* __restrict__ O)
{
    extern __shared__ float sm[];
    float* Ks = sm;                 // [S*Dh]
    float* Vs = sm + S * Dh;        // [S*Dh]
    float* madd = Vs + S * Dh;      // [S]
    const int h = blockIdx.x, b = blockIdx.y;
    const int tid = threadIdx.x;
    const size_t base = (size_t)b * S * H + (size_t)h * Dh;

    for (int i = tid; i < S * 8; i += 256) {
        int row = i >> 3, slot = (i & 7) << 2;
        *(float4*)&Ks[row * Dh + slot] = *(const float4*)&K[base + (size_t)row * H + slot];
        *(float4*)&Vs[row * Dh + slot] = *(const float4*)&V[base + (size_t)row * H + slot];
    }
    madd[tid] = (1.0f - cmask[b * S + tid]) * VERY_NEG;
    __syncthreads();

    float q[32];
    const float* qp = &Q[base + (size_t)tid * H];
    #pragma unroll
    for (int i = 0; i < 32; i += 4) {
        float4 t = *(const float4*)&qp[i];
        q[i] = t.x; q[i + 1] = t.y; q[i + 2] = t.z; q[i + 3] = t.w;
    }
    const float scale = rsqrtf(32.0f);
    float m = -INFINITY, l = 0.f, o[32];
    #pragma unroll
    for (int i = 0; i < 32; i++) o[i] = 0.f;

    for (int k = 0; k < S; k++) {
        const float* kr = &Ks[k * Dh];
        float sc = 0.f;
        #pragma unroll
        for (int i = 0; i < 32; i++) sc = fmaf(q[i], kr[i], sc);
        sc = sc * scale + madd[k];
        float mn = fmaxf(m, sc);
        float corr = __expf(m - mn);
        float p = __expf(sc - mn);
        l = l * corr + p;
        const float* vr = &Vs[k * Dh];
        #pragma unroll
        for (int i = 0; i < 32; i++) o[i] = fmaf(o[i], corr, p * vr[i]);
        m = mn;
    }
    const float inv = 1.0f / l;
    float* op = &O[base + (size_t)tid * H];
    #pragma unroll
    for (int i = 0; i < 32; i += 4) {
        float4 t = make_float4(o[i] * inv, o[i + 1] * inv, o[i + 2] * inv, o[i + 3] * inv);
        *(float4*)&op[i] = t;
    }
}

// ---------------- attention pooling: one block per batch row ------------------
__global__ void pool_kernel(const float* __restrict__ x, const float* __restrict__ cmask,
                            const float* __restrict__ pw, const float* __restrict__ pb,
                            float* __restrict__ out)
{
    __shared__ float spw[H];
    __shared__ float sc[S];
    __shared__ float red[8];
    const int b = blockIdx.x, tid = threadIdx.x;
    const int lane = tid & 31, w = tid >> 5;
    spw[tid] = pw[tid];
    __syncthreads();

    for (int row = w; row < S; row += 8) {
        const float* xp = &x[((size_t)b * S + row) * H];
        float4 a0 = *(const float4*)&xp[lane * 4];
        float4 a1 = *(const float4*)&xp[128 + lane * 4];
        float acc = a0.x * spw[lane * 4 + 0] + a0.y * spw[lane * 4 + 1]
                  + a0.z * spw[lane * 4 + 2] + a0.w * spw[lane * 4 + 3]
                  + a1.x * spw[128 + lane * 4 + 0] + a1.y * spw[128 + lane * 4 + 1]
                  + a1.z * spw[128 + lane * 4 + 2] + a1.w * spw[128 + lane * 4 + 3];
        #pragma unroll
        for (int off = 16; off; off >>= 1) acc += __shfl_xor_sync(0xffffffffu, acc, off);
        if (lane == 0)
            sc[row] = acc + pb[0] + (1.f - cmask[b * S + row]) * VERY_NEG;
    }
    __syncthreads();

    float v = sc[tid];
    float mx = v;
    #pragma unroll
    for (int off = 16; off; off >>= 1) mx = fmaxf(mx, __shfl_xor_sync(0xffffffffu, mx, off));
    if (lane == 0) red[w] = mx;
    __syncthreads();
    float bm = red[0];
    #pragma unroll
    for (int i = 1; i < 8; i++) bm = fmaxf(bm, red[i]);
    __syncthreads();
    float e = __expf(v - bm);
    float su = e;
    #pragma unroll
    for (int off = 16; off; off >>= 1) su += __shfl_xor_sync(0xffffffffu, su, off);
    if (lane == 0) red[w] = su;
    __syncthreads();
    float tot = 0.f;
    #pragma unroll
    for (int i = 0; i < 8; i++) tot += red[i];
    sc[tid] = e / tot;
    __syncthreads();

    float acc = 0.f;
    for (int ss = 0; ss < S; ss++)
        acc = fmaf(sc[ss], x[((size_t)b * S + ss) * H + tid], acc);
    out[(size_t)b * H + tid] = acc;
}

// ---------------- host ---------------------------------------------------------
static void run_encoder(const float* xin, const float* wq, const float* wk, const float* wv,
                        const float* wo, const float* fw1, const float* fb1,
                        const float* fw2, const float* fb2, const float* cmask,
                        float* q, float* k, float* v, float* ctx, float* t, float* ffn,
                        float* xout)
{
    dim3 g2(2, BS / 128), thr(256);
    sgemm_kernel<false, false, false><<<g2, thr>>>(xin, wq, nullptr, nullptr, q, BS, H, H);
    sgemm_kernel<false, false, false><<<g2, thr>>>(xin, wk, nullptr, nullptr, k, BS, H, H);
    sgemm_kernel<false, false, false><<<g2, thr>>>(xin, wv, nullptr, nullptr, v, BS, H, H);
    const int smem = (2 * S * Dh + S) * (int)sizeof(float);
    attention_kernel<<<dim3(NH, Bz), 256, smem>>>(q, k, v, cmask, ctx);
    sgemm_kernel<false, false, true><<<g2, thr>>>(ctx, wo, nullptr, xin, t, BS, H, H);
    sgemm_kernel<true, true, false><<<dim3(FF / 128, BS / 128), thr>>>(t, fw1, fb1, nullptr, ffn, BS, FF, H);
    sgemm_kernel<false, true, true><<<g2, thr>>>(ffn, fw2, fb2, t, xout, BS, H, FF);
}

extern "C" void kernel_launch(void* const* d_in, const int* in_sizes, int n_in,
                              void* d_out, int out_size)
{
    const int*   input_ids   = (const int*)d_in[0];
    const float* code_mask   = (const float*)d_in[1];
    const int*   dx_leaves   = (const int*)d_in[2];
    const int*   dx_anc      = (const int*)d_in[3];
    const float* dx_mask     = (const float*)d_in[4];
    const float* embed_init  = (const float*)d_in[5];
    const float* embed_inp   = (const float*)d_in[6];
    const float* attn_w1     = (const float*)d_in[7];
    const float* attn_b1     = (const float*)d_in[8];
    const float* attn_w2     = (const float*)d_in[9];
    const float* attn_b2     = (const float*)d_in[10];
    const float* pool_w      = (const float*)d_in[11];
    const float* pool_b      = (const float*)d_in[12];
    const float* v_wq  = (const float*)d_in[13];
    const float* v_wk  = (const float*)d_in[14];
    const float* v_wv  = (const float*)d_in[15];
    const float* v_wo  = (const float*)d_in[16];
    const float* v_fw1 = (const float*)d_in[17];
    const float* v_fb1 = (const float*)d_in[18];
    const float* v_fw2 = (const float*)d_in[19];
    const float* v_fb2 = (const float*)d_in[20];
    const float* d_wq  = (const float*)d_in[21];
    const float* d_wk  = (const float*)d_in[22];
    const float* d_wv  = (const float*)d_in[23];
    const float* d_wo  = (const float*)d_in[24];
    const float* d_fw1 = (const float*)d_in[25];
    const float* d_fb1 = (const float*)d_in[26];
    const float* d_fw2 = (const float*)d_in[27];
    const float* d_fb2 = (const float*)d_in[28];
    float* out = (float*)d_out;

    float *xcat, *hid, *sbuf, *dag, *xv, *xd, *t, *q, *k, *v, *ctx, *ffn, *xdo;
    cudaGetSymbolAddress((void**)&xcat, g_xcat);
    cudaGetSymbolAddress((void**)&hid,  g_hid);
    cudaGetSymbolAddress((void**)&sbuf, g_s);
    cudaGetSymbolAddress((void**)&dag,  g_dag);
    cudaGetSymbolAddress((void**)&xv,   g_xv);
    cudaGetSymbolAddress((void**)&xd,   g_xd);
    cudaGetSymbolAddress((void**)&t,    g_t);
    cudaGetSymbolAddress((void**)&q,    g_q);
    cudaGetSymbolAddress((void**)&k,    g_k);
    cudaGetSymbolAddress((void**)&v,    g_v);
    cudaGetSymbolAddress((void**)&ctx,  g_ctx);
    cudaGetSymbolAddress((void**)&ffn,  g_ffn);
    cudaGetSymbolAddress((void**)&xdo,  g_xdo);

    const int asmem = (2 * S * Dh + S) * (int)sizeof(float);
    cudaFuncSetAttribute(attention_kernel, cudaFuncAttributeMaxDynamicSharedMemorySize, asmem);

    // 1) DAG embedding pipeline
    gather_xcat_kernel<<<(CA * 64 + 255) / 256, 256>>>(dx_leaves, dx_anc, dx_mask, embed_init, xcat);
    sgemm_kernel<true, true, false><<<dim3(2, CA / 128), 256>>>(xcat, attn_w1, attn_b1, nullptr,
                                                                hid, CA, H, 2 * H);
    dag_score_kernel<<<CA / 8, 256>>>(hid, attn_w2, attn_b2, sbuf);
    dag_softmax_kernel<<<C / 8, 256>>>(sbuf, dx_mask, xcat, dag);

    // 2) token embeddings for both streams
    embed_gather_kernel<<<(BS * 64 + 255) / 256, 256>>>(input_ids, embed_inp, dag, xv, xd);

    // 3) visit encoder -> writes directly to d_out[0 : BS*H]
    run_encoder(xv, v_wq, v_wk, v_wv, v_wo, v_fw1, v_fb1, v_fw2, v_fb2, code_mask,
                q, k, v, ctx, t, ffn, out);

    // 4) dag encoder -> g_xdo
    run_encoder(xd, d_wq, d_wk, d_wv, d_wo, d_fw1, d_fb1, d_fw2, d_fb2, code_mask,
                q, k, v, ctx, t, ffn, xdo);

    // 5) attention pooling -> d_out[BS*H : BS*H + B*H]
    pool_kernel<<<Bz, 256>>>(xdo, code_mask, pool_w, pool_b, out + (size_t)BS * H);
}

// round 4
// speedup vs baseline: 1.4762x; 1.4762x over previous
#include <cuda_runtime.h>
#include <cuda_bf16.h>
#include <math.h>
#include <stdint.h>

#define VERY_NEG (-1e30f)

// Problem constants (fixed shapes from reference)
constexpr int Bz = 128;
constexpr int S  = 256;
constexpr int H  = 256;
constexpr int NH = 8;
constexpr int Dh = 32;
constexpr int C  = 20000;
constexpr int A  = 8;
constexpr int BS = Bz * S;         // 32768
constexpr int CA = C * A;          // 160000
constexpr int FF = 4 * H;          // 1024

// ---------------- scratch (device globals: allocation-free contract) ----------
__device__ float g_xcat[(size_t)CA * 2 * H];  // [160000, 512] gathered (leaves*m | anc*m)
__device__ float g_hid [(size_t)CA * H];      // [160000, 256]
__device__ float g_s   [CA];                  // [160000]
__device__ float g_dag [(size_t)C * H];       // [20000, 256] dag embeddings
__device__ float g_xv  [(size_t)BS * H];      // visit embed
__device__ float g_xd  [(size_t)BS * H];      // dag embed
__device__ float g_t   [(size_t)BS * H];      // post-wo residual stream
__device__ float g_q   [(size_t)BS * H];
__device__ float g_k   [(size_t)BS * H];
__device__ float g_v   [(size_t)BS * H];
__device__ float g_ctx [(size_t)BS * H];
__device__ float g_ffn [(size_t)BS * FF];
__device__ float g_xdo [(size_t)BS * H];      // dag encoder output (pooled next)

// ---------------- split-bf16 (3xBF16) tensor-core GEMM, 128x128x16 tile -------
// C = [RELU]( A[M,K] @ B[K,N] + bias[N] ) + Res[M,N]
// fp32 inputs split into bf16 hi+lo at smem-store time; inner loop computes
// hi*hi + hi*lo + lo*hi with m16n8k16 bf16 MMA, fp32 accumulate (~16-bit mantissa).
// Requires: M%128==0, N%128==0, K%16==0 (all shapes here satisfy this).

__device__ __forceinline__ void mma_bf16(float* c, const uint32_t* a, const uint32_t* b) {
    asm volatile(
        "mma.sync.aligned.m16n8k16.row.col.f32.bf16.bf16.f32 "
        "{%0,%1,%2,%3}, {%4,%5,%6,%7}, {%8,%9}, {%0,%1,%2,%3};\n"
        : "+f"(c[0]), "+f"(c[1]), "+f"(c[2]), "+f"(c[3])
        : "r"(a[0]), "r"(a[1]), "r"(a[2]), "r"(a[3]),
          "r"(b[0]), "r"(b[1]));
}

__device__ __forceinline__ void split2(float x0, float x1, uint32_t& hi, uint32_t& lo) {
    __nv_bfloat16 h0 = __float2bfloat16_rn(x0);
    __nv_bfloat16 h1 = __float2bfloat16_rn(x1);
    __nv_bfloat16 l0 = __float2bfloat16_rn(x0 - __bfloat162float(h0));
    __nv_bfloat16 l1 = __float2bfloat16_rn(x1 - __bfloat162float(h1));
    hi = ((uint32_t)__bfloat16_as_ushort(h1) << 16) | __bfloat16_as_ushort(h0);
    lo = ((uint32_t)__bfloat16_as_ushort(l1) << 16) | __bfloat16_as_ushort(l0);
}

template <bool RELU, bool BIAS, bool RES>
__global__ __launch_bounds__(256, 1)
void tgemm_kernel(const float* __restrict__ Am, const float* __restrict__ Bm,
                  const float* __restrict__ bias, const float* __restrict__ Res,
                  float* __restrict__ Cm, int M, int N, int K)
{
    // k-pair-packed bf16x2 tiles. A: [row][kpair]; B: [kpair][col] (transposed on store)
    __shared__ uint32_t As_h[2][128][10];
    __shared__ uint32_t As_l[2][128][10];
    __shared__ uint32_t Bs_h[2][8][136];
    __shared__ uint32_t Bs_l[2][8][136];

    const int tid  = threadIdx.x;
    const int lane = tid & 31;
    const int wid  = tid >> 5;
    const int warp_m = wid & 3;        // 4 warps along M (32 rows each)
    const int warp_n = wid >> 2;       // 2 warps along N (64 cols each)
    const int m0 = blockIdx.y * 128, n0 = blockIdx.x * 128;
    const int r = lane >> 2, c = lane & 3;   // groupID / threadID-in-group

    int a_row[2], a_k[2], b_row[2], b_col[2];
    #pragma unroll
    for (int i = 0; i < 2; i++) {
        int idx = tid + i * 256;
        a_row[i] = idx >> 2;  a_k[i]   = (idx & 3) << 2;   // k: 0,4,8,12
        b_row[i] = idx >> 5;  b_col[i] = (idx & 31) << 2;  // k row 0..15
    }

    float acc[2][8][4] = {};
    float4 pa[2], pb[2];

    // ---- smem store helpers (fp32 -> bf16 hi/lo, k-pair packed) ----
    auto store_tile = [&](int buf) {
        #pragma unroll
        for (int i = 0; i < 2; i++) {
            // A: float4 along k -> two packed k-pairs
            uint32_t h01, l01, h23, l23;
            split2(pa[i].x, pa[i].y, h01, l01);
            split2(pa[i].z, pa[i].w, h23, l23);
            const int kp = a_k[i] >> 1;
            As_h[buf][a_row[i]][kp]     = h01;
            As_h[buf][a_row[i]][kp + 1] = h23;
            As_l[buf][a_row[i]][kp]     = l01;
            As_l[buf][a_row[i]][kp + 1] = l23;
            // B: float4 along n, fixed k -> 16-bit halves of 4 packed words
            const int bkp = b_row[i] >> 1, half = b_row[i] & 1;
            float xs[4] = {pb[i].x, pb[i].y, pb[i].z, pb[i].w};
            #pragma unroll
            for (int j = 0; j < 4; j++) {
                __nv_bfloat16 hb = __float2bfloat16_rn(xs[j]);
                __nv_bfloat16 lb = __float2bfloat16_rn(xs[j] - __bfloat162float(hb));
                ((uint16_t*)&Bs_h[buf][bkp][b_col[i] + j])[half] = __bfloat16_as_ushort(hb);
                ((uint16_t*)&Bs_l[buf][bkp][b_col[i] + j])[half] = __bfloat16_as_ushort(lb);
            }
        }
    };

    // prologue: tile 0
    #pragma unroll
    for (int i = 0; i < 2; i++) {
        pa[i] = *(const float4*)&Am[(size_t)(m0 + a_row[i]) * K + a_k[i]];
        pb[i] = *(const float4*)&Bm[(size_t)b_row[i] * N + n0 + b_col[i]];
    }
    store_tile(0);
    __syncthreads();

    const int ntiles = K >> 4;
    for (int t = 0; t < ntiles; t++) {
        const int cur = t & 1;
        if (t + 1 < ntiles) {
            const int k0 = (t + 1) << 4;
            #pragma unroll
            for (int i = 0; i < 2; i++) {
                pa[i] = *(const float4*)&Am[(size_t)(m0 + a_row[i]) * K + k0 + a_k[i]];
                pb[i] = *(const float4*)&Bm[(size_t)(k0 + b_row[i]) * N + n0 + b_col[i]];
            }
        }

        // fragment loads (one k16 chunk per tile)
        uint32_t a_h[2][4], a_l[2][4], b_h[8][2], b_l[8][2];
        #pragma unroll
        for (int mt = 0; mt < 2; mt++) {
            const int row = warp_m * 32 + mt * 16 + r;
            a_h[mt][0] = As_h[cur][row][c];
            a_h[mt][1] = As_h[cur][row + 8][c];
            a_h[mt][2] = As_h[cur][row][c + 4];
            a_h[mt][3] = As_h[cur][row + 8][c + 4];
            a_l[mt][0] = As_l[cur][row][c];
            a_l[mt][1] = As_l[cur][row + 8][c];
            a_l[mt][2] = As_l[cur][row][c + 4];
            a_l[mt][3] = As_l[cur][row + 8][c + 4];
        }
        #pragma unroll
        for (int nt = 0; nt < 8; nt++) {
            const int col = warp_n * 64 + nt * 8 + r;
            b_h[nt][0] = Bs_h[cur][c][col];
            b_h[nt][1] = Bs_h[cur][c + 4][col];
            b_l[nt][0] = Bs_l[cur][c][col];
            b_l[nt][1] = Bs_l[cur][c + 4][col];
        }

        #pragma unroll
        for (int mt = 0; mt < 2; mt++)
            #pragma unroll
            for (int nt = 0; nt < 8; nt++) {
                mma_bf16(acc[mt][nt], a_h[mt], b_h[nt]);
                mma_bf16(acc[mt][nt], a_h[mt], b_l[nt]);
                mma_bf16(acc[mt][nt], a_l[mt], b_h[nt]);
            }

        if (t + 1 < ntiles) {
            store_tile(cur ^ 1);
            __syncthreads();
        }
    }

    // epilogue (fused bias / relu / residual), float2 stores
    #pragma unroll
    for (int mt = 0; mt < 2; mt++) {
        #pragma unroll
        for (int nt = 0; nt < 8; nt++) {
            const int row = m0 + warp_m * 32 + mt * 16 + r;
            const int col = n0 + warp_n * 64 + nt * 8 + 2 * c;
            #pragma unroll
            for (int h = 0; h < 2; h++) {
                float2 v = make_float2(acc[mt][nt][h * 2], acc[mt][nt][h * 2 + 1]);
                if (BIAS) {
                    const float2 bb = *(const float2*)&bias[col];
                    v.x += bb.x; v.y += bb.y;
                }
                if (RELU) { v.x = fmaxf(v.x, 0.f); v.y = fmaxf(v.y, 0.f); }
                const size_t off = (size_t)(row + h * 8) * N + col;
                if (RES) {
                    const float2 rr = *(const float2*)&Res[off];
                    v.x += rr.x; v.y += rr.y;
                }
                *(float2*)&Cm[off] = v;
            }
        }
    }
}

// ---------------- DAG stage kernels -------------------------------------------
__global__ void gather_xcat_kernel(const int* __restrict__ leaves, const int* __restrict__ anc,
                                   const float* __restrict__ mask, const float* __restrict__ emb,
                                   float* __restrict__ xcat)
{
    int idx = blockIdx.x * blockDim.x + threadIdx.x;  // over CA*64 float4 slots
    if (idx >= CA * 64) return;
    int ca = idx >> 6;
    int h4 = (idx & 63) << 2;
    float m = mask[ca];
    int li = leaves[ca], ai = anc[ca];
    float4 lv = *(const float4*)&emb[(size_t)li * H + h4];
    float4 av = *(const float4*)&emb[(size_t)ai * H + h4];
    float4 l2 = make_float4(lv.x * m, lv.y * m, lv.z * m, lv.w * m);
    float4 a2 = make_float4(av.x * m, av.y * m, av.z * m, av.w * m);
    size_t rb = (size_t)ca * 512;
    *(float4*)&xcat[rb + h4] = l2;
    *(float4*)&xcat[rb + 256 + h4] = a2;
}

// s[row] = hid[row,:] . w2 + b2     (one warp per row)
__global__ void dag_score_kernel(const float* __restrict__ hid, const float* __restrict__ w2,
                                 const float* __restrict__ b2, float* __restrict__ s)
{
    int gw = (blockIdx.x * blockDim.x + threadIdx.x) >> 5;
    int lane = threadIdx.x & 31;
    if (gw >= CA) return;
    const float* hp = hid + (size_t)gw * H;
    float4 h0 = *(const float4*)&hp[lane * 4];
    float4 h1 = *(const float4*)&hp[128 + lane * 4];
    float4 w0 = *(const float4*)&w2[lane * 4];
    float4 w1 = *(const float4*)&w2[128 + lane * 4];
    float acc = h0.x * w0.x + h0.y * w0.y + h0.z * w0.z + h0.w * w0.w
              + h1.x * w1.x + h1.y * w1.y + h1.z * w1.z + h1.w * w1.w;
    #pragma unroll
    for (int off = 16; off; off >>= 1) acc += __shfl_xor_sync(0xffffffffu, acc, off);
    if (lane == 0) s[gw] = acc + b2[0];
}

// per code: softmax over A=8 (masked) then dag[c,:] = sum_a w[a] * (anc*m)[c,a,:]
__global__ void dag_softmax_kernel(const float* __restrict__ s, const float* __restrict__ mask,
                                   const float* __restrict__ xcat, float* __restrict__ dag)
{
    int gw = (blockIdx.x * blockDim.x + threadIdx.x) >> 5;  // one warp per code
    int lane = threadIdx.x & 31;
    if (gw >= C) return;
    float sv = -3.0e38f;
    if (lane < 8) {
        float m = mask[gw * 8 + lane];
        sv = s[gw * 8 + lane] + (1.f - m) * VERY_NEG;
    }
    float mx = sv;
    #pragma unroll
    for (int off = 4; off; off >>= 1) mx = fmaxf(mx, __shfl_xor_sync(0xffffffffu, mx, off));
    float e = (lane < 8) ? __expf(sv - mx) : 0.f;
    float su = e;
    #pragma unroll
    for (int off = 4; off; off >>= 1) su += __shfl_xor_sync(0xffffffffu, su, off);
    float wv = e / su;
    float w8[8];
    #pragma unroll
    for (int a = 0; a < 8; a++) w8[a] = __shfl_sync(0xffffffffu, wv, a);

    const float4* xc4 = (const float4*)xcat;
    const size_t rowbase = (size_t)gw * 8 * 128 + 64;  // anc half, in float4 units
    #pragma unroll
    for (int rep = 0; rep < 2; rep++) {
        int f4i = lane + rep * 32;  // 0..63
        float4 acc = make_float4(0.f, 0.f, 0.f, 0.f);
        #pragma unroll
        for (int a = 0; a < 8; a++) {
            float4 v = xc4[rowbase + (size_t)a * 128 + f4i];
            acc.x = fmaf(w8[a], v.x, acc.x);
            acc.y = fmaf(w8[a], v.y, acc.y);
            acc.z = fmaf(w8[a], v.z, acc.z);
            acc.w = fmaf(w8[a], v.w, acc.w);
        }
        ((float4*)dag)[(size_t)gw * 64 + f4i] = acc;
    }
}

// embed both streams: xv = embed_inputs[id]; xd = (id==0) ? 0 : dag[id-1]
__global__ void embed_gather_kernel(const int* __restrict__ ids, const float* __restrict__ embw,
                                    const float* __restrict__ dag, float* __restrict__ xv,
                                    float* __restrict__ xd)
{
    int idx = blockIdx.x * blockDim.x + threadIdx.x;  // BS*64
    if (idx >= BS * 64) return;
    int bs = idx >> 6, h4 = idx & 63;
    int id = ids[bs];
    ((float4*)xv)[(size_t)bs * 64 + h4] = ((const float4*)embw)[(size_t)id * 64 + h4];
    float4 dv = make_float4(0.f, 0.f, 0.f, 0.f);
    if (id > 0) dv = ((const float4*)dag)[(size_t)(id - 1) * 64 + h4];
    ((float4*)xd)[(size_t)bs * 64 + h4] = dv;
}

// ---------------- attention: one block per (b, head), one query per thread ----
__global__ void attention_kernel(const float* __restrict__ Q, const float* __restrict__ K,
                                 const float* __restrict__ V, const float* __restrict__ cmask,
                                 float* __restrict__ O)
{
    extern __shared__ float sm[];
    float* Ks = sm;                 // [S*Dh]
    float* Vs = sm + S * Dh;        // [S*Dh]
    float* madd = Vs + S * Dh;      // [S]
    const int h = blockIdx.x, b = blockIdx.y;
    const int tid = threadIdx.x;
    const size_t base = (size_t)b * S * H + (size_t)h * Dh;

    for (int i = tid; i < S * 8; i += 256) {
        int row = i >> 3, slot = (i & 7) << 2;
        *(float4*)&Ks[row * Dh + slot] = *(const float4*)&K[base + (size_t)row * H + slot];
        *(float4*)&Vs[row * Dh + slot] = *(const float4*)&V[base + (size_t)row * H + slot];
    }
    madd[tid] = (1.0f - cmask[b * S + tid]) * VERY_NEG;
    __syncthreads();

    float q[32];
    const float* qp = &Q[base + (size_t)tid * H];
    #pragma unroll
    for (int i = 0; i < 32; i += 4) {
        float4 t = *(const float4*)&qp[i];
        q[i] = t.x; q[i + 1] = t.y; q[i + 2] = t.z; q[i + 3] = t.w;
    }
    const float scale = rsqrtf(32.0f);
    float m = -INFINITY, l = 0.f, o[32];
    #pragma unroll
    for (int i = 0; i < 32; i++) o[i] = 0.f;

    for (int k = 0; k < S; k++) {
        const float* kr = &Ks[k * Dh];
        float sc = 0.f;
        #pragma unroll
        for (int i = 0; i < 32; i++) sc = fmaf(q[i], kr[i], sc);
        sc = sc * scale + madd[k];
        float mn = fmaxf(m, sc);
        float corr = __expf(m - mn);
        float p = __expf(sc - mn);
        l = l * corr + p;
        const float* vr = &Vs[k * Dh];
        #pragma unroll
        for (int i = 0; i < 32; i++) o[i] = fmaf(o[i], corr, p * vr[i]);
        m = mn;
    }
    const float inv = 1.0f / l;
    float* op = &O[base + (size_t)tid * H];
    #pragma unroll
    for (int i = 0; i < 32; i += 4) {
        float4 t = make_float4(o[i] * inv, o[i + 1] * inv, o[i + 2] * inv, o[i + 3] * inv);
        *(float4*)&op[i] = t;
    }
}

// ---------------- attention pooling: one block per batch row ------------------
__global__ void pool_kernel(const float* __restrict__ x, const float* __restrict__ cmask,
                            const float* __restrict__ pw, const float* __restrict__ pb,
                            float* __restrict__ out)
{
    __shared__ float spw[H];
    __shared__ float sc[S];
    __shared__ float red[8];
    const int b = blockIdx.x, tid = threadIdx.x;
    const int lane = tid & 31, w = tid >> 5;
    spw[tid] = pw[tid];
    __syncthreads();

    for (int row = w; row < S; row += 8) {
        const float* xp = &x[((size_t)b * S + row) * H];
        float4 a0 = *(const float4*)&xp[lane * 4];
        float4 a1 = *(const float4*)&xp[128 + lane * 4];
        float acc = a0.x * spw[lane * 4 + 0] + a0.y * spw[lane * 4 + 1]
                  + a0.z * spw[lane * 4 + 2] + a0.w * spw[lane * 4 + 3]
                  + a1.x * spw[128 + lane * 4 + 0] + a1.y * spw[128 + lane * 4 + 1]
                  + a1.z * spw[128 + lane * 4 + 2] + a1.w * spw[128 + lane * 4 + 3];
        #pragma unroll
        for (int off = 16; off; off >>= 1) acc += __shfl_xor_sync(0xffffffffu, acc, off);
        if (lane == 0)
            sc[row] = acc + pb[0] + (1.f - cmask[b * S + row]) * VERY_NEG;
    }
    __syncthreads();

    float v = sc[tid];
    float mx = v;
    #pragma unroll
    for (int off = 16; off; off >>= 1) mx = fmaxf(mx, __shfl_xor_sync(0xffffffffu, mx, off));
    if (lane == 0) red[w] = mx;
    __syncthreads();
    float bm = red[0];
    #pragma unroll
    for (int i = 1; i < 8; i++) bm = fmaxf(bm, red[i]);
    __syncthreads();
    float e = __expf(v - bm);
    float su = e;
    #pragma unroll
    for (int off = 16; off; off >>= 1) su += __shfl_xor_sync(0xffffffffu, su, off);
    if (lane == 0) red[w] = su;
    __syncthreads();
    float tot = 0.f;
    #pragma unroll
    for (int i = 0; i < 8; i++) tot += red[i];
    sc[tid] = e / tot;
    __syncthreads();

    float acc = 0.f;
    for (int ss = 0; ss < S; ss++)
        acc = fmaf(sc[ss], x[((size_t)b * S + ss) * H + tid], acc);
    out[(size_t)b * H + tid] = acc;
}

// ---------------- host ---------------------------------------------------------
static void run_encoder(const float* xin, const float* wq, const float* wk, const float* wv,
                        const float* wo, const float* fw1, const float* fb1,
                        const float* fw2, const float* fb2, const float* cmask,
                        float* q, float* k, float* v, float* ctx, float* t, float* ffn,
                        float* xout)
{
    dim3 g2(2, BS / 128), thr(256);
    tgemm_kernel<false, false, false><<<g2, thr>>>(xin, wq, nullptr, nullptr, q, BS, H, H);
    tgemm_kernel<false, false, false><<<g2, thr>>>(xin, wk, nullptr, nullptr, k, BS, H, H);
    tgemm_kernel<false, false, false><<<g2, thr>>>(xin, wv, nullptr, nullptr, v, BS, H, H);
    const int smem = (2 * S * Dh + S) * (int)sizeof(float);
    attention_kernel<<<dim3(NH, Bz), 256, smem>>>(q, k, v, cmask, ctx);
    tgemm_kernel<false, false, true><<<g2, thr>>>(ctx, wo, nullptr, xin, t, BS, H, H);
    tgemm_kernel<true, true, false><<<dim3(FF / 128, BS / 128), thr>>>(t, fw1, fb1, nullptr, ffn, BS, FF, H);
    tgemm_kernel<false, true, true><<<g2, thr>>>(ffn, fw2, fb2, t, xout, BS, H, FF);
}

extern "C" void kernel_launch(void* const* d_in, const int* in_sizes, int n_in,
                              void* d_out, int out_size)
{
    const int*   input_ids   = (const int*)d_in[0];
    const float* code_mask   = (const float*)d_in[1];
    const int*   dx_leaves   = (const int*)d_in[2];
    const int*   dx_anc      = (const int*)d_in[3];
    const float* dx_mask     = (const float*)d_in[4];
    const float* embed_init  = (const float*)d_in[5];
    const float* embed_inp   = (const float*)d_in[6];
    const float* attn_w1     = (const float*)d_in[7];
    const float* attn_b1     = (const float*)d_in[8];
    const float* attn_w2     = (const float*)d_in[9];
    const float* attn_b2     = (const float*)d_in[10];
    const float* pool_w      = (const float*)d_in[11];
    const float* pool_b      = (const float*)d_in[12];
    const float* v_wq  = (const float*)d_in[13];
    const float* v_wk  = (const float*)d_in[14];
    const float* v_wv  = (const float*)d_in[15];
    const float* v_wo  = (const float*)d_in[16];
    const float* v_fw1 = (const float*)d_in[17];
    const float* v_fb1 = (const float*)d_in[18];
    const float* v_fw2 = (const float*)d_in[19];
    const float* v_fb2 = (const float*)d_in[20];
    const float* d_wq  = (const float*)d_in[21];
    const float* d_wk  = (const float*)d_in[22];
    const float* d_wv  = (const float*)d_in[23];
    const float* d_wo  = (const float*)d_in[24];
    const float* d_fw1 = (const float*)d_in[25];
    const float* d_fb1 = (const float*)d_in[26];
    const float* d_fw2 = (const float*)d_in[27];
    const float* d_fb2 = (const float*)d_in[28];
    float* out = (float*)d_out;

    float *xcat, *hid, *sbuf, *dag, *xv, *xd, *t, *q, *k, *v, *ctx, *ffn, *xdo;
    cudaGetSymbolAddress((void**)&xcat, g_xcat);
    cudaGetSymbolAddress((void**)&hid,  g_hid);
    cudaGetSymbolAddress((void**)&sbuf, g_s);
    cudaGetSymbolAddress((void**)&dag,  g_dag);
    cudaGetSymbolAddress((void**)&xv,   g_xv);
    cudaGetSymbolAddress((void**)&xd,   g_xd);
    cudaGetSymbolAddress((void**)&t,    g_t);
    cudaGetSymbolAddress((void**)&q,    g_q);
    cudaGetSymbolAddress((void**)&k,    g_k);
    cudaGetSymbolAddress((void**)&v,    g_v);
    cudaGetSymbolAddress((void**)&ctx,  g_ctx);
    cudaGetSymbolAddress((void**)&ffn,  g_ffn);
    cudaGetSymbolAddress((void**)&xdo,  g_xdo);

    const int asmem = (2 * S * Dh + S) * (int)sizeof(float);
    cudaFuncSetAttribute(attention_kernel, cudaFuncAttributeMaxDynamicSharedMemorySize, asmem);

    // 1) DAG embedding pipeline
    gather_xcat_kernel<<<(CA * 64 + 255) / 256, 256>>>(dx_leaves, dx_anc, dx_mask, embed_init, xcat);
    tgemm_kernel<true, true, false><<<dim3(2, CA / 128), 256>>>(xcat, attn_w1, attn_b1, nullptr,
                                                                hid, CA, H, 2 * H);
    dag_score_kernel<<<CA / 8, 256>>>(hid, attn_w2, attn_b2, sbuf);
    dag_softmax_kernel<<<C / 8, 256>>>(sbuf, dx_mask, xcat, dag);

    // 2) token embeddings for both streams
    embed_gather_kernel<<<(BS * 64 + 255) / 256, 256>>>(input_ids, embed_inp, dag, xv, xd);

    // 3) visit encoder -> writes directly to d_out[0 : BS*H]
    run_encoder(xv, v_wq, v_wk, v_wv, v_wo, v_fw1, v_fb1, v_fw2, v_fb2, code_mask,
                q, k, v, ctx, t, ffn, out);

    // 4) dag encoder -> g_xdo
    run_encoder(xd, d_wq, d_wk, d_wv, d_wo, d_fw1, d_fb1, d_fw2, d_fb2, code_mask,
                q, k, v, ctx, t, ffn, xdo);

    // 5) attention pooling -> d_out[BS*H : BS*H + B*H]
    pool_kernel<<<Bz, 256>>>(xdo, code_mask, pool_w, pool_b, out + (size_t)BS * H);
}

// round 5
// speedup vs baseline: 1.7870x; 1.2105x over previous
#include <cuda_runtime.h>
#include <cuda_bf16.h>
#include <math.h>
#include <stdint.h>

#define VERY_NEG (-1e30f)

constexpr int Bz = 128;
constexpr int S  = 256;
constexpr int H  = 256;
constexpr int NH = 8;
constexpr int Dh = 32;
constexpr int C  = 20000;
constexpr int A  = 8;
constexpr int BS = Bz * S;         // 32768
constexpr int CA = C * A;          // 160000
constexpr int FF = 4 * H;          // 1024

// ---------------- scratch (device globals: allocation-free contract) ----------
__device__ float g_hid [(size_t)CA * H];      // [160000, 256]
__device__ float g_s   [CA];                  // [160000]
__device__ float g_dag [(size_t)C * H];       // [20000, 256]
__device__ float g_xv  [(size_t)BS * H];
__device__ float g_xd  [(size_t)BS * H];
__device__ float g_t   [(size_t)BS * H];
__device__ float g_q   [(size_t)BS * H];
__device__ float g_k   [(size_t)BS * H];
__device__ float g_v   [(size_t)BS * H];
__device__ float g_ctx [(size_t)BS * H];
__device__ float g_ffn [(size_t)BS * FF];
__device__ float g_xdo [(size_t)BS * H];

// ---------------- split-bf16 (3xBF16) tensor-core GEMM, 128x128x16 tile -------
// C = [RELU]( A[M,K] @ B[K,N] + bias[N] ) + Res[M,N]
// GATHER variant: A row r, col k comes from emb[(k<256?leaves[r]:anc[r])*256 + (k&255)] * mask[r]

__device__ __forceinline__ void mma_bf16(float* c, const uint32_t* a, const uint32_t* b) {
    asm volatile(
        "mma.sync.aligned.m16n8k16.row.col.f32.bf16.bf16.f32 "
        "{%0,%1,%2,%3}, {%4,%5,%6,%7}, {%8,%9}, {%0,%1,%2,%3};\n"
        : "+f"(c[0]), "+f"(c[1]), "+f"(c[2]), "+f"(c[3])
        : "r"(a[0]), "r"(a[1]), "r"(a[2]), "r"(a[3]),
          "r"(b[0]), "r"(b[1]));
}

__device__ __forceinline__ void split2(float x0, float x1, uint32_t& hi, uint32_t& lo) {
    __nv_bfloat16 h0 = __float2bfloat16_rn(x0);
    __nv_bfloat16 h1 = __float2bfloat16_rn(x1);
    __nv_bfloat16 l0 = __float2bfloat16_rn(x0 - __bfloat162float(h0));
    __nv_bfloat16 l1 = __float2bfloat16_rn(x1 - __bfloat162float(h1));
    hi = ((uint32_t)__bfloat16_as_ushort(h1) << 16) | __bfloat16_as_ushort(h0);
    lo = ((uint32_t)__bfloat16_as_ushort(l1) << 16) | __bfloat16_as_ushort(l0);
}

template <bool RELU, bool BIAS, bool RES, bool GATHER>
__global__ __launch_bounds__(256, 2)
void tgemm_kernel(const float* __restrict__ Am, const float* __restrict__ Bm,
                  const float* __restrict__ bias, const float* __restrict__ Res,
                  float* __restrict__ Cm, int M, int N, int K,
                  const int* __restrict__ gl, const int* __restrict__ ga,
                  const float* __restrict__ gm)
{
    __shared__ uint32_t As_h[2][128][10];
    __shared__ uint32_t As_l[2][128][10];
    __shared__ uint32_t Bs_h[2][8][136];
    __shared__ uint32_t Bs_l[2][8][136];

    const int tid  = threadIdx.x;
    const int lane = tid & 31;
    const int wid  = tid >> 5;
    const int warp_m = wid & 3;
    const int warp_n = wid >> 2;
    const int m0 = blockIdx.y * 128, n0 = blockIdx.x * 128;
    const int r = lane >> 2, c = lane & 3;

    int a_row[2], a_k[2], b_row[2], b_col[2];
    #pragma unroll
    for (int i = 0; i < 2; i++) {
        int idx = tid + i * 256;
        a_row[i] = idx >> 2;  a_k[i]   = (idx & 3) << 2;
        b_row[i] = idx >> 5;  b_col[i] = (idx & 31) << 2;
    }

    // per-thread gather metadata (row fixed across tiles)
    int   grow_l[2], grow_a[2];
    float grow_m[2];
    if (GATHER) {
        #pragma unroll
        for (int i = 0; i < 2; i++) {
            const int row = m0 + a_row[i];
            grow_l[i] = gl[row];
            grow_a[i] = ga[row];
            grow_m[i] = gm[row];
        }
    }

    float acc[2][8][4] = {};
    float4 pa[2], pb[2];

    auto load_a = [&](int k0) {
        #pragma unroll
        for (int i = 0; i < 2; i++) {
            if (GATHER) {
                const int k = k0 + a_k[i];
                const int src = (k < 256) ? grow_l[i] : grow_a[i];
                float4 v = *(const float4*)&Am[(size_t)src * 256 + (k & 255)];
                pa[i] = make_float4(v.x * grow_m[i], v.y * grow_m[i],
                                    v.z * grow_m[i], v.w * grow_m[i]);
            } else {
                pa[i] = *(const float4*)&Am[(size_t)(m0 + a_row[i]) * K + k0 + a_k[i]];
            }
            pb[i] = *(const float4*)&Bm[(size_t)(k0 + b_row[i]) * N + n0 + b_col[i]];
        }
    };

    auto store_tile = [&](int buf) {
        #pragma unroll
        for (int i = 0; i < 2; i++) {
            uint32_t h01, l01, h23, l23;
            split2(pa[i].x, pa[i].y, h01, l01);
            split2(pa[i].z, pa[i].w, h23, l23);
            const int kp = a_k[i] >> 1;
            As_h[buf][a_row[i]][kp]     = h01;
            As_h[buf][a_row[i]][kp + 1] = h23;
            As_l[buf][a_row[i]][kp]     = l01;
            As_l[buf][a_row[i]][kp + 1] = l23;
            const int bkp = b_row[i] >> 1, half = b_row[i] & 1;
            float xs[4] = {pb[i].x, pb[i].y, pb[i].z, pb[i].w};
            #pragma unroll
            for (int j = 0; j < 4; j++) {
                __nv_bfloat16 hb = __float2bfloat16_rn(xs[j]);
                __nv_bfloat16 lb = __float2bfloat16_rn(xs[j] - __bfloat162float(hb));
                ((uint16_t*)&Bs_h[buf][bkp][b_col[i] + j])[half] = __bfloat16_as_ushort(hb);
                ((uint16_t*)&Bs_l[buf][bkp][b_col[i] + j])[half] = __bfloat16_as_ushort(lb);
            }
        }
    };

    load_a(0);
    store_tile(0);
    __syncthreads();

    const int ntiles = K >> 4;
    for (int t = 0; t < ntiles; t++) {
        const int cur = t & 1;
        if (t + 1 < ntiles) load_a((t + 1) << 4);

        uint32_t a_h[2][4], a_l[2][4], b_h[8][2], b_l[8][2];
        #pragma unroll
        for (int mt = 0; mt < 2; mt++) {
            const int row = warp_m * 32 + mt * 16 + r;
            a_h[mt][0] = As_h[cur][row][c];
            a_h[mt][1] = As_h[cur][row + 8][c];
            a_h[mt][2] = As_h[cur][row][c + 4];
            a_h[mt][3] = As_h[cur][row + 8][c + 4];
            a_l[mt][0] = As_l[cur][row][c];
            a_l[mt][1] = As_l[cur][row + 8][c];
            a_l[mt][2] = As_l[cur][row][c + 4];
            a_l[mt][3] = As_l[cur][row + 8][c + 4];
        }
        #pragma unroll
        for (int nt = 0; nt < 8; nt++) {
            const int col = warp_n * 64 + nt * 8 + r;
            b_h[nt][0] = Bs_h[cur][c][col];
            b_h[nt][1] = Bs_h[cur][c + 4][col];
            b_l[nt][0] = Bs_l[cur][c][col];
            b_l[nt][1] = Bs_l[cur][c + 4][col];
        }

        #pragma unroll
        for (int mt = 0; mt < 2; mt++)
            #pragma unroll
            for (int nt = 0; nt < 8; nt++) {
                mma_bf16(acc[mt][nt], a_h[mt], b_h[nt]);
                mma_bf16(acc[mt][nt], a_h[mt], b_l[nt]);
                mma_bf16(acc[mt][nt], a_l[mt], b_h[nt]);
            }

        if (t + 1 < ntiles) {
            store_tile(cur ^ 1);
            __syncthreads();
        }
    }

    #pragma unroll
    for (int mt = 0; mt < 2; mt++) {
        #pragma unroll
        for (int nt = 0; nt < 8; nt++) {
            const int row = m0 + warp_m * 32 + mt * 16 + r;
            const int col = n0 + warp_n * 64 + nt * 8 + 2 * c;
            #pragma unroll
            for (int h = 0; h < 2; h++) {
                float2 v = make_float2(acc[mt][nt][h * 2], acc[mt][nt][h * 2 + 1]);
                if (BIAS) {
                    const float2 bb = *(const float2*)&bias[col];
                    v.x += bb.x; v.y += bb.y;
                }
                if (RELU) { v.x = fmaxf(v.x, 0.f); v.y = fmaxf(v.y, 0.f); }
                const size_t off = (size_t)(row + h * 8) * N + col;
                if (RES) {
                    const float2 rr = *(const float2*)&Res[off];
                    v.x += rr.x; v.y += rr.y;
                }
                *(float2*)&Cm[off] = v;
            }
        }
    }
}

// ---------------- DAG stage kernels -------------------------------------------
// s[row] = hid[row,:] . w2 + b2     (one warp per row)
__global__ void dag_score_kernel(const float* __restrict__ hid, const float* __restrict__ w2,
                                 const float* __restrict__ b2, float* __restrict__ s)
{
    int gw = (blockIdx.x * blockDim.x + threadIdx.x) >> 5;
    int lane = threadIdx.x & 31;
    if (gw >= CA) return;
    const float* hp = hid + (size_t)gw * H;
    float4 h0 = *(const float4*)&hp[lane * 4];
    float4 h1 = *(const float4*)&hp[128 + lane * 4];
    float4 w0 = *(const float4*)&w2[lane * 4];
    float4 w1 = *(const float4*)&w2[128 + lane * 4];
    float acc = h0.x * w0.x + h0.y * w0.y + h0.z * w0.z + h0.w * w0.w
              + h1.x * w1.x + h1.y * w1.y + h1.z * w1.z + h1.w * w1.w;
    #pragma unroll
    for (int off = 16; off; off >>= 1) acc += __shfl_xor_sync(0xffffffffu, acc, off);
    if (lane == 0) s[gw] = acc + b2[0];
}

// per code: masked softmax over A=8, then dag[c,:] = sum_a w[a] * emb[anc[c,a],:]
// (mask factor folded into w: masked slots get w=0)
__global__ void dag_softmax_kernel(const float* __restrict__ s, const float* __restrict__ mask,
                                   const int* __restrict__ anc, const float* __restrict__ emb,
                                   float* __restrict__ dag)
{
    int gw = (blockIdx.x * blockDim.x + threadIdx.x) >> 5;
    int lane = threadIdx.x & 31;
    if (gw >= C) return;
    float sv = -3.0e38f;
    int av = 0;
    if (lane < 8) {
        float m = mask[gw * 8 + lane];
        sv = s[gw * 8 + lane] + (1.f - m) * VERY_NEG;
        av = anc[gw * 8 + lane];
    }
    float mx = sv;
    #pragma unroll
    for (int off = 4; off; off >>= 1) mx = fmaxf(mx, __shfl_xor_sync(0xffffffffu, mx, off));
    float e = (lane < 8) ? __expf(sv - mx) : 0.f;
    float su = e;
    #pragma unroll
    for (int off = 4; off; off >>= 1) su += __shfl_xor_sync(0xffffffffu, su, off);
    float wv = e / su;
    float w8[8];
    int   a8[8];
    #pragma unroll
    for (int a = 0; a < 8; a++) {
        w8[a] = __shfl_sync(0xffffffffu, wv, a);
        a8[a] = __shfl_sync(0xffffffffu, av, a);
    }

    const float4* e4 = (const float4*)emb;
    #pragma unroll
    for (int rep = 0; rep < 2; rep++) {
        int f4i = lane + rep * 32;
        float4 acc = make_float4(0.f, 0.f, 0.f, 0.f);
        #pragma unroll
        for (int a = 0; a < 8; a++) {
            float4 v = e4[(size_t)a8[a] * 64 + f4i];
            acc.x = fmaf(w8[a], v.x, acc.x);
            acc.y = fmaf(w8[a], v.y, acc.y);
            acc.z = fmaf(w8[a], v.z, acc.z);
            acc.w = fmaf(w8[a], v.w, acc.w);
        }
        ((float4*)dag)[(size_t)gw * 64 + f4i] = acc;
    }
}

// embed both streams
__global__ void embed_gather_kernel(const int* __restrict__ ids, const float* __restrict__ embw,
                                    const float* __restrict__ dag, float* __restrict__ xv,
                                    float* __restrict__ xd)
{
    int idx = blockIdx.x * blockDim.x + threadIdx.x;
    if (idx >= BS * 64) return;
    int bs = idx >> 6, h4 = idx & 63;
    int id = ids[bs];
    ((float4*)xv)[(size_t)bs * 64 + h4] = ((const float4*)embw)[(size_t)id * 64 + h4];
    float4 dv = make_float4(0.f, 0.f, 0.f, 0.f);
    if (id > 0) dv = ((const float4*)dag)[(size_t)(id - 1) * 64 + h4];
    ((float4*)xd)[(size_t)bs * 64 + h4] = dv;
}

// ---------------- attention: chunked online softmax, 1 query/thread -----------
__global__ void attention_kernel(const float* __restrict__ Q, const float* __restrict__ K,
                                 const float* __restrict__ V, const float* __restrict__ cmask,
                                 float* __restrict__ O)
{
    extern __shared__ float sm[];
    float* Ks = sm;                 // [S*Dh]
    float* Vs = sm + S * Dh;        // [S*Dh]
    float* madd = Vs + S * Dh;      // [S]
    const int h = blockIdx.x, b = blockIdx.y;
    const int tid = threadIdx.x;
    const size_t base = (size_t)b * S * H + (size_t)h * Dh;

    for (int i = tid; i < S * 8; i += 256) {
        int row = i >> 3, slot = (i & 7) << 2;
        *(float4*)&Ks[row * Dh + slot] = *(const float4*)&K[base + (size_t)row * H + slot];
        *(float4*)&Vs[row * Dh + slot] = *(const float4*)&V[base + (size_t)row * H + slot];
    }
    madd[tid] = (1.0f - cmask[b * S + tid]) * VERY_NEG;
    __syncthreads();

    float q[32];
    const float* qp = &Q[base + (size_t)tid * H];
    #pragma unroll
    for (int i = 0; i < 32; i += 4) {
        float4 t = *(const float4*)&qp[i];
        q[i] = t.x; q[i + 1] = t.y; q[i + 2] = t.z; q[i + 3] = t.w;
    }
    const float scale = rsqrtf(32.0f);
    float m = -INFINITY, l = 0.f, o[32];
    #pragma unroll
    for (int i = 0; i < 32; i++) o[i] = 0.f;

    for (int k0 = 0; k0 < S; k0 += 16) {
        float sc[16];
        float cm = -INFINITY;
        #pragma unroll
        for (int kk = 0; kk < 16; kk++) {
            const float* kr = &Ks[(k0 + kk) * Dh];
            float d = 0.f;
            #pragma unroll
            for (int i = 0; i < 32; i++) d = fmaf(q[i], kr[i], d);
            sc[kk] = d * scale + madd[k0 + kk];
            cm = fmaxf(cm, sc[kk]);
        }
        const float mn = fmaxf(m, cm);
        const float corr = __expf(m - mn);
        l *= corr;
        #pragma unroll
        for (int i = 0; i < 32; i++) o[i] *= corr;
        #pragma unroll
        for (int kk = 0; kk < 16; kk++) {
            const float p = __expf(sc[kk] - mn);
            l += p;
            const float* vr = &Vs[(k0 + kk) * Dh];
            #pragma unroll
            for (int i = 0; i < 32; i++) o[i] = fmaf(p, vr[i], o[i]);
        }
        m = mn;
    }
    const float inv = 1.0f / l;
    float* op = &O[base + (size_t)tid * H];
    #pragma unroll
    for (int i = 0; i < 32; i += 4) {
        float4 t = make_float4(o[i] * inv, o[i + 1] * inv, o[i + 2] * inv, o[i + 3] * inv);
        *(float4*)&op[i] = t;
    }
}

// ---------------- attention pooling -------------------------------------------
__global__ void pool_kernel(const float* __restrict__ x, const float* __restrict__ cmask,
                            const float* __restrict__ pw, const float* __restrict__ pb,
                            float* __restrict__ out)
{
    __shared__ float spw[H];
    __shared__ float sc[S];
    __shared__ float red[8];
    const int b = blockIdx.x, tid = threadIdx.x;
    const int lane = tid & 31, w = tid >> 5;
    spw[tid] = pw[tid];
    __syncthreads();

    for (int row = w; row < S; row += 8) {
        const float* xp = &x[((size_t)b * S + row) * H];
        float4 a0 = *(const float4*)&xp[lane * 4];
        float4 a1 = *(const float4*)&xp[128 + lane * 4];
        float acc = a0.x * spw[lane * 4 + 0] + a0.y * spw[lane * 4 + 1]
                  + a0.z * spw[lane * 4 + 2] + a0.w * spw[lane * 4 + 3]
                  + a1.x * spw[128 + lane * 4 + 0] + a1.y * spw[128 + lane * 4 + 1]
                  + a1.z * spw[128 + lane * 4 + 2] + a1.w * spw[128 + lane * 4 + 3];
        #pragma unroll
        for (int off = 16; off; off >>= 1) acc += __shfl_xor_sync(0xffffffffu, acc, off);
        if (lane == 0)
            sc[row] = acc + pb[0] + (1.f - cmask[b * S + row]) * VERY_NEG;
    }
    __syncthreads();

    float v = sc[tid];
    float mx = v;
    #pragma unroll
    for (int off = 16; off; off >>= 1) mx = fmaxf(mx, __shfl_xor_sync(0xffffffffu, mx, off));
    if (lane == 0) red[w] = mx;
    __syncthreads();
    float bm = red[0];
    #pragma unroll
    for (int i = 1; i < 8; i++) bm = fmaxf(bm, red[i]);
    __syncthreads();
    float e = __expf(v - bm);
    float su = e;
    #pragma unroll
    for (int off = 16; off; off >>= 1) su += __shfl_xor_sync(0xffffffffu, su, off);
    if (lane == 0) red[w] = su;
    __syncthreads();
    float tot = 0.f;
    #pragma unroll
    for (int i = 0; i < 8; i++) tot += red[i];
    sc[tid] = e / tot;
    __syncthreads();

    float acc = 0.f;
    for (int ss = 0; ss < S; ss++)
        acc = fmaf(sc[ss], x[((size_t)b * S + ss) * H + tid], acc);
    out[(size_t)b * H + tid] = acc;
}

// ---------------- host ---------------------------------------------------------
static void run_encoder(const float* xin, const float* wq, const float* wk, const float* wv,
                        const float* wo, const float* fw1, const float* fb1,
                        const float* fw2, const float* fb2, const float* cmask,
                        float* q, float* k, float* v, float* ctx, float* t, float* ffn,
                        float* xout)
{
    dim3 g2(2, BS / 128), thr(256);
    tgemm_kernel<false, false, false, false><<<g2, thr>>>(xin, wq, nullptr, nullptr, q, BS, H, H, nullptr, nullptr, nullptr);
    tgemm_kernel<false, false, false, false><<<g2, thr>>>(xin, wk, nullptr, nullptr, k, BS, H, H, nullptr, nullptr, nullptr);
    tgemm_kernel<false, false, false, false><<<g2, thr>>>(xin, wv, nullptr, nullptr, v, BS, H, H, nullptr, nullptr, nullptr);
    const int smem = (2 * S * Dh + S) * (int)sizeof(float);
    attention_kernel<<<dim3(NH, Bz), 256, smem>>>(q, k, v, cmask, ctx);
    tgemm_kernel<false, false, true, false><<<g2, thr>>>(ctx, wo, nullptr, xin, t, BS, H, H, nullptr, nullptr, nullptr);
    tgemm_kernel<true, true, false, false><<<dim3(FF / 128, BS / 128), thr>>>(t, fw1, fb1, nullptr, ffn, BS, FF, H, nullptr, nullptr, nullptr);
    tgemm_kernel<false, true, true, false><<<g2, thr>>>(ffn, fw2, fb2, t, xout, BS, H, FF, nullptr, nullptr, nullptr);
}

extern "C" void kernel_launch(void* const* d_in, const int* in_sizes, int n_in,
                              void* d_out, int out_size)
{
    const int*   input_ids   = (const int*)d_in[0];
    const float* code_mask   = (const float*)d_in[1];
    const int*   dx_leaves   = (const int*)d_in[2];
    const int*   dx_anc      = (const int*)d_in[3];
    const float* dx_mask     = (const float*)d_in[4];
    const float* embed_init  = (const float*)d_in[5];
    const float* embed_inp   = (const float*)d_in[6];
    const float* attn_w1     = (const float*)d_in[7];
    const float* attn_b1     = (const float*)d_in[8];
    const float* attn_w2     = (const float*)d_in[9];
    const float* attn_b2     = (const float*)d_in[10];
    const float* pool_w      = (const float*)d_in[11];
    const float* pool_b      = (const float*)d_in[12];
    const float* v_wq  = (const float*)d_in[13];
    const float* v_wk  = (const float*)d_in[14];
    const float* v_wv  = (const float*)d_in[15];
    const float* v_wo  = (const float*)d_in[16];
    const float* v_fw1 = (const float*)d_in[17];
    const float* v_fb1 = (const float*)d_in[18];
    const float* v_fw2 = (const float*)d_in[19];
    const float* v_fb2 = (const float*)d_in[20];
    const float* d_wq  = (const float*)d_in[21];
    const float* d_wk  = (const float*)d_in[22];
    const float* d_wv  = (const float*)d_in[23];
    const float* d_wo  = (const float*)d_in[24];
    const float* d_fw1 = (const float*)d_in[25];
    const float* d_fb1 = (const float*)d_in[26];
    const float* d_fw2 = (const float*)d_in[27];
    const float* d_fb2 = (const float*)d_in[28];
    float* out = (float*)d_out;

    float *hid, *sbuf, *dag, *xv, *xd, *t, *q, *k, *v, *ctx, *ffn, *xdo;
    cudaGetSymbolAddress((void**)&hid,  g_hid);
    cudaGetSymbolAddress((void**)&sbuf, g_s);
    cudaGetSymbolAddress((void**)&dag,  g_dag);
    cudaGetSymbolAddress((void**)&xv,   g_xv);
    cudaGetSymbolAddress((void**)&xd,   g_xd);
    cudaGetSymbolAddress((void**)&t,    g_t);
    cudaGetSymbolAddress((void**)&q,    g_q);
    cudaGetSymbolAddress((void**)&k,    g_k);
    cudaGetSymbolAddress((void**)&v,    g_v);
    cudaGetSymbolAddress((void**)&ctx,  g_ctx);
    cudaGetSymbolAddress((void**)&ffn,  g_ffn);
    cudaGetSymbolAddress((void**)&xdo,  g_xdo);

    const int asmem = (2 * S * Dh + S) * (int)sizeof(float);
    cudaFuncSetAttribute(attention_kernel, cudaFuncAttributeMaxDynamicSharedMemorySize, asmem);

    // 1) DAG MLP with fused gather (A rows built from embed_init + indices + mask)
    tgemm_kernel<true, true, false, true><<<dim3(2, CA / 128), 256>>>(
        embed_init, attn_w1, attn_b1, nullptr, hid, CA, H, 2 * H,
        dx_leaves, dx_anc, dx_mask);
    dag_score_kernel<<<CA / 8, 256>>>(hid, attn_w2, attn_b2, sbuf);
    dag_softmax_kernel<<<C / 8, 256>>>(sbuf, dx_mask, dx_anc, embed_init, dag);

    // 2) token embeddings
    embed_gather_kernel<<<(BS * 64 + 255) / 256, 256>>>(input_ids, embed_inp, dag, xv, xd);

    // 3) visit encoder -> d_out[0 : BS*H]
    run_encoder(xv, v_wq, v_wk, v_wv, v_wo, v_fw1, v_fb1, v_fw2, v_fb2, code_mask,
                q, k, v, ctx, t, ffn, out);

    // 4) dag encoder -> g_xdo
    run_encoder(xd, d_wq, d_wk, d_wv, d_wo, d_fw1, d_fb1, d_fw2, d_fb2, code_mask,
                q, k, v, ctx, t, ffn, xdo);

    // 5) pooling -> d_out[BS*H : ]
    pool_kernel<<<Bz, 256>>>(xdo, code_mask, pool_w, pool_b, out + (size_t)BS * H);
}

// round 6
// speedup vs baseline: 1.9251x; 1.0773x over previous
#include <cuda_runtime.h>
#include <cuda_bf16.h>
#include <math.h>
#include <stdint.h>

#define VERY_NEG (-1e30f)

constexpr int Bz = 128;
constexpr int S  = 256;
constexpr int H  = 256;
constexpr int NH = 8;
constexpr int Dh = 32;
constexpr int C  = 20000;
constexpr int A  = 8;
constexpr int BS = Bz * S;         // 32768
constexpr int CA = C * A;          // 160000
constexpr int FF = 4 * H;          // 1024
constexpr int NODES1 = 25001;      // NODES+1
constexpr int QKVN = 3 * H;        // 768

// ---------------- scratch ------------------------------------------------------
__device__ uint32_t g_eh [(size_t)NODES1 * 128];   // packed emb_init hi (k-pairs)
__device__ uint32_t g_el [(size_t)NODES1 * 128];
__device__ float    g_s  [CA];
__device__ float    g_dag[(size_t)C * H];
__device__ float    g_xv [(size_t)BS * H];
__device__ float    g_xd [(size_t)BS * H];
__device__ uint32_t g_xvh[(size_t)BS * 128], g_xvl[(size_t)BS * 128];
__device__ uint32_t g_xdh[(size_t)BS * 128], g_xdl[(size_t)BS * 128];
__device__ float    g_qkv[(size_t)BS * QKVN];
__device__ uint32_t g_cth[(size_t)BS * 128], g_ctl[(size_t)BS * 128];
__device__ float    g_t  [(size_t)BS * H];
__device__ uint32_t g_th [(size_t)BS * 128], g_tl [(size_t)BS * 128];
__device__ uint32_t g_fh [(size_t)BS * 512], g_fl [(size_t)BS * 512];
__device__ float    g_xdo[(size_t)BS * H];
// weight packs (reused by both encoders)
__device__ uint32_t g_wqkvh[128 * QKVN], g_wqkvl[128 * QKVN];
__device__ uint32_t g_woh [128 * 256],  g_wol [128 * 256];
__device__ uint32_t g_f1h [128 * 1024], g_f1l [128 * 1024];
__device__ uint32_t g_f2h [512 * 256],  g_f2l [512 * 256];
__device__ uint32_t g_w1h [256 * 256],  g_w1l [256 * 256];

// ---------------- helpers ------------------------------------------------------
__device__ __forceinline__ void mma_bf16(float* c, const uint32_t* a, const uint32_t* b) {
    asm volatile(
        "mma.sync.aligned.m16n8k16.row.col.f32.bf16.bf16.f32 "
        "{%0,%1,%2,%3}, {%4,%5,%6,%7}, {%8,%9}, {%0,%1,%2,%3};\n"
        : "+f"(c[0]), "+f"(c[1]), "+f"(c[2]), "+f"(c[3])
        : "r"(a[0]), "r"(a[1]), "r"(a[2]), "r"(a[3]),
          "r"(b[0]), "r"(b[1]));
}

__device__ __forceinline__ void split2(float x0, float x1, uint32_t& hi, uint32_t& lo) {
    __nv_bfloat16 h0 = __float2bfloat16_rn(x0);
    __nv_bfloat16 h1 = __float2bfloat16_rn(x1);
    __nv_bfloat16 l0 = __float2bfloat16_rn(x0 - __bfloat162float(h0));
    __nv_bfloat16 l1 = __float2bfloat16_rn(x1 - __bfloat162float(h1));
    hi = ((uint32_t)__bfloat16_as_ushort(h1) << 16) | __bfloat16_as_ushort(h0);
    lo = ((uint32_t)__bfloat16_as_ushort(l1) << 16) | __bfloat16_as_ushort(l0);
}

// pack contiguous fp32 pairs (A-style, k-contiguous) -> hi/lo words
__global__ void pack_contig_kernel(const float* __restrict__ src, uint32_t* __restrict__ dh,
                                   uint32_t* __restrict__ dl, int n2)
{
    int idx = blockIdx.x * blockDim.x + threadIdx.x;
    if (idx >= n2) return;
    float2 v = ((const float2*)src)[idx];
    uint32_t h, l;
    split2(v.x, v.y, h, l);
    dh[idx] = h; dl[idx] = l;
}

// pack B [K][Nsrc] fp32 -> [K/2][Ndst] k-pair words at column offset
__global__ void pack_B_kernel(const float* __restrict__ src, uint32_t* __restrict__ dh,
                              uint32_t* __restrict__ dl, int Khalf, int Nsrc, int Ndst, int coff)
{
    int idx = blockIdx.x * blockDim.x + threadIdx.x;
    if (idx >= Khalf * Nsrc) return;
    int kp = idx / Nsrc, n = idx - kp * Nsrc;
    float a = src[(size_t)(2 * kp) * Nsrc + n];
    float b = src[(size_t)(2 * kp + 1) * Nsrc + n];
    uint32_t h, l;
    split2(a, b, h, l);
    dh[(size_t)kp * Ndst + coff + n] = h;
    dl[(size_t)kp * Ndst + coff + n] = l;
}

__global__ void s_init_kernel(float* __restrict__ s, const float* __restrict__ b2)
{
    int idx = blockIdx.x * blockDim.x + threadIdx.x;
    if (idx < CA) s[idx] = b2[0];
}

// ---------------- split-bf16 tensor GEMM on pre-packed inputs ------------------
// C = [RELU]( A @ B + bias ) + Res ; optional fused outputs:
//   OUTF32: fp32 C; SPLIT: packed bf16 hi/lo C; SCORE: s[row](+=) C_row . w2
// GATHER: A row r col k from packed emb[(k<256?gl[r]:ga[r])][...] (mask dropped: dead math)
template <bool RELU, bool BIAS, bool RES, bool GATHER, bool OUTF32, bool SPLIT, bool SCORE>
__global__ __launch_bounds__(256, 2)
void tgemm_kernel(const uint32_t* __restrict__ Ah, const uint32_t* __restrict__ Al,
                  const uint32_t* __restrict__ Bh, const uint32_t* __restrict__ Bl,
                  const float* __restrict__ bias, const float* __restrict__ Res,
                  float* __restrict__ Cm, uint32_t* __restrict__ Ch, uint32_t* __restrict__ Cl,
                  const float* __restrict__ w2, float* __restrict__ sout,
                  int M, int N, int K,
                  const int* __restrict__ gl, const int* __restrict__ ga)
{
    __shared__ uint32_t As_h[2][128][10];
    __shared__ uint32_t As_l[2][128][10];
    __shared__ uint32_t Bs_h[2][8][136];
    __shared__ uint32_t Bs_l[2][8][136];

    const int tid  = threadIdx.x;
    const int lane = tid & 31;
    const int wid  = tid >> 5;
    const int warp_m = wid & 3;
    const int warp_n = wid >> 2;
    const int m0 = blockIdx.y * 128, n0 = blockIdx.x * 128;
    const int r = lane >> 2, c = lane & 3;
    const int Khalf = K >> 1;

    int arow[2], akp2[2], bkp[2], bcol2[2];
    #pragma unroll
    for (int i = 0; i < 2; i++) {
        int idx = tid + i * 256;
        arow[i] = idx >> 2;  akp2[i]  = (idx & 3) << 1;   // kpair 0,2,4,6
        bkp[i]  = idx >> 6;  bcol2[i] = (idx & 63) << 1;
    }

    int grow_l[2], grow_a[2];
    if (GATHER) {
        #pragma unroll
        for (int i = 0; i < 2; i++) {
            grow_l[i] = gl[m0 + arow[i]];
            grow_a[i] = ga[m0 + arow[i]];
        }
    }

    float acc[2][8][4] = {};
    uint2 pah[2], pal[2], pbh[2], pbl[2];

    auto load_tile = [&](int k0) {
        const int kpb = k0 >> 1;
        #pragma unroll
        for (int i = 0; i < 2; i++) {
            size_t aaddr;
            if (GATHER) {
                const int kglob = k0 + akp2[i] * 2;
                const int src = (kglob < 256) ? grow_l[i] : grow_a[i];
                aaddr = (size_t)src * 128 + ((kpb + akp2[i]) & 127);
            } else {
                aaddr = (size_t)(m0 + arow[i]) * Khalf + kpb + akp2[i];
            }
            pah[i] = *(const uint2*)&Ah[aaddr];
            pal[i] = *(const uint2*)&Al[aaddr];
            const size_t baddr = (size_t)(kpb + bkp[i]) * N + n0 + bcol2[i];
            pbh[i] = *(const uint2*)&Bh[baddr];
            pbl[i] = *(const uint2*)&Bl[baddr];
        }
    };

    auto store_tile = [&](int buf) {
        #pragma unroll
        for (int i = 0; i < 2; i++) {
            As_h[buf][arow[i]][akp2[i]]     = pah[i].x;
            As_h[buf][arow[i]][akp2[i] + 1] = pah[i].y;
            As_l[buf][arow[i]][akp2[i]]     = pal[i].x;
            As_l[buf][arow[i]][akp2[i] + 1] = pal[i].y;
            Bs_h[buf][bkp[i]][bcol2[i]]     = pbh[i].x;
            Bs_h[buf][bkp[i]][bcol2[i] + 1] = pbh[i].y;
            Bs_l[buf][bkp[i]][bcol2[i]]     = pbl[i].x;
            Bs_l[buf][bkp[i]][bcol2[i] + 1] = pbl[i].y;
        }
    };

    load_tile(0);
    store_tile(0);
    __syncthreads();

    const int ntiles = K >> 4;
    for (int t = 0; t < ntiles; t++) {
        const int cur = t & 1;
        if (t + 1 < ntiles) load_tile((t + 1) << 4);

        uint32_t a_h[2][4], a_l[2][4], b_h[8][2], b_l[8][2];
        #pragma unroll
        for (int mt = 0; mt < 2; mt++) {
            const int row = warp_m * 32 + mt * 16 + r;
            a_h[mt][0] = As_h[cur][row][c];
            a_h[mt][1] = As_h[cur][row + 8][c];
            a_h[mt][2] = As_h[cur][row][c + 4];
            a_h[mt][3] = As_h[cur][row + 8][c + 4];
            a_l[mt][0] = As_l[cur][row][c];
            a_l[mt][1] = As_l[cur][row + 8][c];
            a_l[mt][2] = As_l[cur][row][c + 4];
            a_l[mt][3] = As_l[cur][row + 8][c + 4];
        }
        #pragma unroll
        for (int nt = 0; nt < 8; nt++) {
            const int col = warp_n * 64 + nt * 8 + r;
            b_h[nt][0] = Bs_h[cur][c][col];
            b_h[nt][1] = Bs_h[cur][c + 4][col];
            b_l[nt][0] = Bs_l[cur][c][col];
            b_l[nt][1] = Bs_l[cur][c + 4][col];
        }

        #pragma unroll
        for (int mt = 0; mt < 2; mt++)
            #pragma unroll
            for (int nt = 0; nt < 8; nt++) {
                mma_bf16(acc[mt][nt], a_h[mt], b_h[nt]);
                mma_bf16(acc[mt][nt], a_h[mt], b_l[nt]);
                mma_bf16(acc[mt][nt], a_l[mt], b_h[nt]);
            }

        if (t + 1 < ntiles) {
            store_tile(cur ^ 1);
            __syncthreads();
        }
    }

    float partial[4] = {0.f, 0.f, 0.f, 0.f};

    #pragma unroll
    for (int mt = 0; mt < 2; mt++) {
        #pragma unroll
        for (int nt = 0; nt < 8; nt++) {
            const int row0 = m0 + warp_m * 32 + mt * 16 + r;
            const int col  = n0 + warp_n * 64 + nt * 8 + 2 * c;
            #pragma unroll
            for (int h = 0; h < 2; h++) {
                float2 v = make_float2(acc[mt][nt][h * 2], acc[mt][nt][h * 2 + 1]);
                if (BIAS) {
                    const float2 bb = *(const float2*)&bias[col];
                    v.x += bb.x; v.y += bb.y;
                }
                if (RELU) { v.x = fmaxf(v.x, 0.f); v.y = fmaxf(v.y, 0.f); }
                const int row = row0 + h * 8;
                const size_t off = (size_t)row * N + col;
                if (RES) {
                    const float2 rr = *(const float2*)&Res[off];
                    v.x += rr.x; v.y += rr.y;
                }
                if (SCORE) {
                    const float2 ww = *(const float2*)&w2[col];
                    partial[mt * 2 + h] += v.x * ww.x + v.y * ww.y;
                }
                if (OUTF32) *(float2*)&Cm[off] = v;
                if (SPLIT) {
                    uint32_t hw, lw;
                    split2(v.x, v.y, hw, lw);
                    Ch[(size_t)row * (N >> 1) + (col >> 1)] = hw;
                    Cl[(size_t)row * (N >> 1) + (col >> 1)] = lw;
                }
            }
        }
    }

    if (SCORE) {
        #pragma unroll
        for (int mt = 0; mt < 2; mt++)
            #pragma unroll
            for (int h = 0; h < 2; h++) {
                float p = partial[mt * 2 + h];
                p += __shfl_xor_sync(0xffffffffu, p, 1);
                p += __shfl_xor_sync(0xffffffffu, p, 2);
                if ((lane & 3) == 0) {
                    const int row = m0 + warp_m * 32 + mt * 16 + r + h * 8;
                    atomicAdd(&sout[row], p);
                }
            }
    }
}

// ---------------- DAG softmax + weighted ancestor sum --------------------------
__global__ void dag_softmax_kernel(const float* __restrict__ s, const float* __restrict__ mask,
                                   const int* __restrict__ anc, const float* __restrict__ emb,
                                   float* __restrict__ dag)
{
    int gw = (blockIdx.x * blockDim.x + threadIdx.x) >> 5;
    int lane = threadIdx.x & 31;
    if (gw >= C) return;
    float sv = -3.0e38f;
    int av = 0;
    if (lane < 8) {
        float m = mask[gw * 8 + lane];
        sv = s[gw * 8 + lane] + (1.f - m) * VERY_NEG;
        av = anc[gw * 8 + lane];
    }
    float mx = sv;
    #pragma unroll
    for (int off = 4; off; off >>= 1) mx = fmaxf(mx, __shfl_xor_sync(0xffffffffu, mx, off));
    float e = (lane < 8) ? __expf(sv - mx) : 0.f;
    float su = e;
    #pragma unroll
    for (int off = 4; off; off >>= 1) su += __shfl_xor_sync(0xffffffffu, su, off);
    float wv = e / su;
    float w8[8];
    int   a8[8];
    #pragma unroll
    for (int a = 0; a < 8; a++) {
        w8[a] = __shfl_sync(0xffffffffu, wv, a);
        a8[a] = __shfl_sync(0xffffffffu, av, a);
    }

    const float4* e4 = (const float4*)emb;
    #pragma unroll
    for (int rep = 0; rep < 2; rep++) {
        int f4i = lane + rep * 32;
        float4 acc = make_float4(0.f, 0.f, 0.f, 0.f);
        #pragma unroll
        for (int a = 0; a < 8; a++) {
            float4 v = e4[(size_t)a8[a] * 64 + f4i];
            acc.x = fmaf(w8[a], v.x, acc.x);
            acc.y = fmaf(w8[a], v.y, acc.y);
            acc.z = fmaf(w8[a], v.z, acc.z);
            acc.w = fmaf(w8[a], v.w, acc.w);
        }
        ((float4*)dag)[(size_t)gw * 64 + f4i] = acc;
    }
}

// embed both streams: fp32 + packed bf16 hi/lo
__global__ void embed_gather_kernel(const int* __restrict__ ids, const float* __restrict__ embw,
                                    const float* __restrict__ dag,
                                    float* __restrict__ xv, float* __restrict__ xd,
                                    uint32_t* __restrict__ xvh, uint32_t* __restrict__ xvl,
                                    uint32_t* __restrict__ xdh, uint32_t* __restrict__ xdl)
{
    int idx = blockIdx.x * blockDim.x + threadIdx.x;
    if (idx >= BS * 64) return;
    int bs = idx >> 6, h4 = idx & 63;
    int id = ids[bs];
    float4 vv = ((const float4*)embw)[(size_t)id * 64 + h4];
    ((float4*)xv)[(size_t)bs * 64 + h4] = vv;
    float4 dv = make_float4(0.f, 0.f, 0.f, 0.f);
    if (id > 0) dv = ((const float4*)dag)[(size_t)(id - 1) * 64 + h4];
    ((float4*)xd)[(size_t)bs * 64 + h4] = dv;

    uint32_t h0, l0, h1, l1;
    split2(vv.x, vv.y, h0, l0);
    split2(vv.z, vv.w, h1, l1);
    xvh[(size_t)bs * 128 + h4 * 2]     = h0;
    xvh[(size_t)bs * 128 + h4 * 2 + 1] = h1;
    xvl[(size_t)bs * 128 + h4 * 2]     = l0;
    xvl[(size_t)bs * 128 + h4 * 2 + 1] = l1;
    split2(dv.x, dv.y, h0, l0);
    split2(dv.z, dv.w, h1, l1);
    xdh[(size_t)bs * 128 + h4 * 2]     = h0;
    xdh[(size_t)bs * 128 + h4 * 2 + 1] = h1;
    xdl[(size_t)bs * 128 + h4 * 2]     = l0;
    xdl[(size_t)bs * 128 + h4 * 2 + 1] = l1;
}

// ---------------- attention: fused QKV input, packed ctx output ----------------
__global__ void attention_kernel(const float* __restrict__ QKV, const float* __restrict__ cmask,
                                 uint32_t* __restrict__ cth, uint32_t* __restrict__ ctl)
{
    extern __shared__ float sm[];
    float* Ks = sm;
    float* Vs = sm + S * Dh;
    float* madd = Vs + S * Dh;
    const int h = blockIdx.x, b = blockIdx.y;
    const int tid = threadIdx.x;
    const size_t rowbase = (size_t)b * S * QKVN;
    const int qo = h * Dh, ko = H + h * Dh, vo = 2 * H + h * Dh;

    for (int i = tid; i < S * 8; i += 256) {
        int row = i >> 3, slot = (i & 7) << 2;
        *(float4*)&Ks[row * Dh + slot] = *(const float4*)&QKV[rowbase + (size_t)row * QKVN + ko + slot];
        *(float4*)&Vs[row * Dh + slot] = *(const float4*)&QKV[rowbase + (size_t)row * QKVN + vo + slot];
    }
    madd[tid] = (1.0f - cmask[b * S + tid]) * VERY_NEG;
    __syncthreads();

    float q[32];
    const float* qp = &QKV[rowbase + (size_t)tid * QKVN + qo];
    #pragma unroll
    for (int i = 0; i < 32; i += 4) {
        float4 t = *(const float4*)&qp[i];
        q[i] = t.x; q[i + 1] = t.y; q[i + 2] = t.z; q[i + 3] = t.w;
    }
    const float scale = rsqrtf(32.0f);
    float m = -INFINITY, l = 0.f, o[32];
    #pragma unroll
    for (int i = 0; i < 32; i++) o[i] = 0.f;

    for (int k0 = 0; k0 < S; k0 += 16) {
        float sc[16];
        float cm = -INFINITY;
        #pragma unroll
        for (int kk = 0; kk < 16; kk++) {
            const float* kr = &Ks[(k0 + kk) * Dh];
            float d = 0.f;
            #pragma unroll
            for (int i = 0; i < 32; i++) d = fmaf(q[i], kr[i], d);
            sc[kk] = d * scale + madd[k0 + kk];
            cm = fmaxf(cm, sc[kk]);
        }
        const float mn = fmaxf(m, cm);
        const float corr = __expf(m - mn);
        l *= corr;
        #pragma unroll
        for (int i = 0; i < 32; i++) o[i] *= corr;
        #pragma unroll
        for (int kk = 0; kk < 16; kk++) {
            const float p = __expf(sc[kk] - mn);
            l += p;
            const float* vr = &Vs[(k0 + kk) * Dh];
            #pragma unroll
            for (int i = 0; i < 32; i++) o[i] = fmaf(p, vr[i], o[i]);
        }
        m = mn;
    }
    const float inv = 1.0f / l;
    const size_t prow = (size_t)(b * S + tid) * 128 + h * 16;
    #pragma unroll
    for (int i = 0; i < 32; i += 2) {
        uint32_t hw, lw;
        split2(o[i] * inv, o[i + 1] * inv, hw, lw);
        cth[prow + i / 2] = hw;
        ctl[prow + i / 2] = lw;
    }
}

// ---------------- attention pooling --------------------------------------------
__global__ void pool_kernel(const float* __restrict__ x, const float* __restrict__ cmask,
                            const float* __restrict__ pw, const float* __restrict__ pb,
                            float* __restrict__ out)
{
    __shared__ float spw[H];
    __shared__ float sc[S];
    __shared__ float red[8];
    const int b = blockIdx.x, tid = threadIdx.x;
    const int lane = tid & 31, w = tid >> 5;
    spw[tid] = pw[tid];
    __syncthreads();

    for (int row = w; row < S; row += 8) {
        const float* xp = &x[((size_t)b * S + row) * H];
        float4 a0 = *(const float4*)&xp[lane * 4];
        float4 a1 = *(const float4*)&xp[128 + lane * 4];
        float acc = a0.x * spw[lane * 4 + 0] + a0.y * spw[lane * 4 + 1]
                  + a0.z * spw[lane * 4 + 2] + a0.w * spw[lane * 4 + 3]
                  + a1.x * spw[128 + lane * 4 + 0] + a1.y * spw[128 + lane * 4 + 1]
                  + a1.z * spw[128 + lane * 4 + 2] + a1.w * spw[128 + lane * 4 + 3];
        #pragma unroll
        for (int off = 16; off; off >>= 1) acc += __shfl_xor_sync(0xffffffffu, acc, off);
        if (lane == 0)
            sc[row] = acc + pb[0] + (1.f - cmask[b * S + row]) * VERY_NEG;
    }
    __syncthreads();

    float v = sc[tid];
    float mx = v;
    #pragma unroll
    for (int off = 16; off; off >>= 1) mx = fmaxf(mx, __shfl_xor_sync(0xffffffffu, mx, off));
    if (lane == 0) red[w] = mx;
    __syncthreads();
    float bm = red[0];
    #pragma unroll
    for (int i = 1; i < 8; i++) bm = fmaxf(bm, red[i]);
    __syncthreads();
    float e = __expf(v - bm);
    float su = e;
    #pragma unroll
    for (int off = 16; off; off >>= 1) su += __shfl_xor_sync(0xffffffffu, su, off);
    if (lane == 0) red[w] = su;
    __syncthreads();
    float tot = 0.f;
    #pragma unroll
    for (int i = 0; i < 8; i++) tot += red[i];
    sc[tid] = e / tot;
    __syncthreads();

    float acc = 0.f;
    for (int ss = 0; ss < S; ss++)
        acc = fmaf(sc[ss], x[((size_t)b * S + ss) * H + tid], acc);
    out[(size_t)b * H + tid] = acc;
}

// ---------------- host ----------------------------------------------------------
struct Ptrs {
    uint32_t *eh, *el, *xvh, *xvl, *xdh, *xdl, *cth, *ctl, *th, *tl, *fh, *fl;
    uint32_t *wqkvh, *wqkvl, *woh, *wol, *f1h, *f1l, *f2h, *f2l, *w1h, *w1l;
    float *s, *dag, *xv, *xd, *qkv, *t, *xdo;
};

static void run_encoder(const Ptrs& P,
                        const uint32_t* xinh, const uint32_t* xinl, const float* xin,
                        const float* wq, const float* wk, const float* wv, const float* wo,
                        const float* fw1, const float* fb1, const float* fw2, const float* fb2,
                        const float* cmask, float* xout)
{
    const int PT = 256;
    // pack weights
    pack_B_kernel<<<(128 * 256 + PT - 1) / PT, PT>>>(wq, P.wqkvh, P.wqkvl, 128, 256, QKVN, 0);
    pack_B_kernel<<<(128 * 256 + PT - 1) / PT, PT>>>(wk, P.wqkvh, P.wqkvl, 128, 256, QKVN, 256);
    pack_B_kernel<<<(128 * 256 + PT - 1) / PT, PT>>>(wv, P.wqkvh, P.wqkvl, 128, 256, QKVN, 512);
    pack_B_kernel<<<(128 * 256 + PT - 1) / PT, PT>>>(wo, P.woh, P.wol, 128, 256, 256, 0);
    pack_B_kernel<<<(128 * 1024 + PT - 1) / PT, PT>>>(fw1, P.f1h, P.f1l, 128, 1024, 1024, 0);
    pack_B_kernel<<<(512 * 256 + PT - 1) / PT, PT>>>(fw2, P.f2h, P.f2l, 512, 256, 256, 0);

    dim3 thr(256);
    // fused QKV
    tgemm_kernel<false, false, false, false, true, false, false><<<dim3(QKVN / 128, BS / 128), thr>>>(
        xinh, xinl, P.wqkvh, P.wqkvl, nullptr, nullptr, P.qkv, nullptr, nullptr,
        nullptr, nullptr, BS, QKVN, H, nullptr, nullptr);
    const int smem = (2 * S * Dh + S) * (int)sizeof(float);
    attention_kernel<<<dim3(NH, Bz), 256, smem>>>(P.qkv, cmask, P.cth, P.ctl);
    // wo + residual, emit fp32 t and packed t
    tgemm_kernel<false, false, true, false, true, true, false><<<dim3(2, BS / 128), thr>>>(
        P.cth, P.ctl, P.woh, P.wol, nullptr, xin, P.t, P.th, P.tl,
        nullptr, nullptr, BS, H, H, nullptr, nullptr);
    // ffn1: packed-only output
    tgemm_kernel<true, true, false, false, false, true, false><<<dim3(FF / 128, BS / 128), thr>>>(
        P.th, P.tl, P.f1h, P.f1l, fb1, nullptr, nullptr, P.fh, P.fl,
        nullptr, nullptr, BS, FF, H, nullptr, nullptr);
    // ffn2: fp32 out + residual
    tgemm_kernel<false, true, true, false, true, false, false><<<dim3(2, BS / 128), thr>>>(
        P.fh, P.fl, P.f2h, P.f2l, fb2, P.t, xout, nullptr, nullptr,
        nullptr, nullptr, BS, H, FF, nullptr, nullptr);
}

extern "C" void kernel_launch(void* const* d_in, const int* in_sizes, int n_in,
                              void* d_out, int out_size)
{
    const int*   input_ids   = (const int*)d_in[0];
    const float* code_mask   = (const float*)d_in[1];
    const int*   dx_leaves   = (const int*)d_in[2];
    const int*   dx_anc      = (const int*)d_in[3];
    const float* dx_mask     = (const float*)d_in[4];
    const float* embed_init  = (const float*)d_in[5];
    const float* embed_inp   = (const float*)d_in[6];
    const float* attn_w1     = (const float*)d_in[7];
    const float* attn_b1     = (const float*)d_in[8];
    const float* attn_w2     = (const float*)d_in[9];
    const float* attn_b2     = (const float*)d_in[10];
    const float* pool_w      = (const float*)d_in[11];
    const float* pool_b      = (const float*)d_in[12];
    const float* v_wq  = (const float*)d_in[13];
    const float* v_wk  = (const float*)d_in[14];
    const float* v_wv  = (const float*)d_in[15];
    const float* v_wo  = (const float*)d_in[16];
    const float* v_fw1 = (const float*)d_in[17];
    const float* v_fb1 = (const float*)d_in[18];
    const float* v_fw2 = (const float*)d_in[19];
    const float* v_fb2 = (const float*)d_in[20];
    const float* d_wq  = (const float*)d_in[21];
    const float* d_wk  = (const float*)d_in[22];
    const float* d_wv  = (const float*)d_in[23];
    const float* d_wo  = (const float*)d_in[24];
    const float* d_fw1 = (const float*)d_in[25];
    const float* d_fb1 = (const float*)d_in[26];
    const float* d_fw2 = (const float*)d_in[27];
    const float* d_fb2 = (const float*)d_in[28];
    float* out = (float*)d_out;

    Ptrs P;
    cudaGetSymbolAddress((void**)&P.eh, g_eh);   cudaGetSymbolAddress((void**)&P.el, g_el);
    cudaGetSymbolAddress((void**)&P.s, g_s);     cudaGetSymbolAddress((void**)&P.dag, g_dag);
    cudaGetSymbolAddress((void**)&P.xv, g_xv);   cudaGetSymbolAddress((void**)&P.xd, g_xd);
    cudaGetSymbolAddress((void**)&P.xvh, g_xvh); cudaGetSymbolAddress((void**)&P.xvl, g_xvl);
    cudaGetSymbolAddress((void**)&P.xdh, g_xdh); cudaGetSymbolAddress((void**)&P.xdl, g_xdl);
    cudaGetSymbolAddress((void**)&P.qkv, g_qkv);
    cudaGetSymbolAddress((void**)&P.cth, g_cth); cudaGetSymbolAddress((void**)&P.ctl, g_ctl);
    cudaGetSymbolAddress((void**)&P.t, g_t);
    cudaGetSymbolAddress((void**)&P.th, g_th);   cudaGetSymbolAddress((void**)&P.tl, g_tl);
    cudaGetSymbolAddress((void**)&P.fh, g_fh);   cudaGetSymbolAddress((void**)&P.fl, g_fl);
    cudaGetSymbolAddress((void**)&P.xdo, g_xdo);
    cudaGetSymbolAddress((void**)&P.wqkvh, g_wqkvh); cudaGetSymbolAddress((void**)&P.wqkvl, g_wqkvl);
    cudaGetSymbolAddress((void**)&P.woh, g_woh); cudaGetSymbolAddress((void**)&P.wol, g_wol);
    cudaGetSymbolAddress((void**)&P.f1h, g_f1h); cudaGetSymbolAddress((void**)&P.f1l, g_f1l);
    cudaGetSymbolAddress((void**)&P.f2h, g_f2h); cudaGetSymbolAddress((void**)&P.f2l, g_f2l);
    cudaGetSymbolAddress((void**)&P.w1h, g_w1h); cudaGetSymbolAddress((void**)&P.w1l, g_w1l);

    const int asmem = (2 * S * Dh + S) * (int)sizeof(float);
    cudaFuncSetAttribute(attention_kernel, cudaFuncAttributeMaxDynamicSharedMemorySize, asmem);

    const int PT = 256;
    // pack emb_init + DAG MLP weight
    pack_contig_kernel<<<(NODES1 * 128 + PT - 1) / PT, PT>>>(embed_init, P.eh, P.el, NODES1 * 128);
    pack_B_kernel<<<(256 * 256 + PT - 1) / PT, PT>>>(attn_w1, P.w1h, P.w1l, 256, 256, 256, 0);
    s_init_kernel<<<(CA + PT - 1) / PT, PT>>>(P.s, attn_b2);

    // DAG MLP: gathered A, relu+bias, fused score into s (no hid materialization)
    tgemm_kernel<true, true, false, true, false, false, true><<<dim3(2, CA / 128), 256>>>(
        P.eh, P.el, P.w1h, P.w1l, attn_b1, nullptr, nullptr, nullptr, nullptr,
        attn_w2, P.s, CA, 256, 512, dx_leaves, dx_anc);
    dag_softmax_kernel<<<C / 8, 256>>>(P.s, dx_mask, dx_anc, embed_init, P.dag);

    embed_gather_kernel<<<(BS * 64 + PT - 1) / PT, PT>>>(input_ids, embed_inp, P.dag,
                                                         P.xv, P.xd, P.xvh, P.xvl, P.xdh, P.xdl);

    // visit encoder -> d_out
    run_encoder(P, P.xvh, P.xvl, P.xv, v_wq, v_wk, v_wv, v_wo, v_fw1, v_fb1, v_fw2, v_fb2,
                code_mask, out);
    // dag encoder -> xdo
    run_encoder(P, P.xdh, P.xdl, P.xd, d_wq, d_wk, d_wv, d_wo, d_fw1, d_fb1, d_fw2, d_fb2,
                code_mask, P.xdo);

    pool_kernel<<<Bz, 256>>>(P.xdo, code_mask, pool_w, pool_b, out + (size_t)BS * H);
}

// round 8
// speedup vs baseline: 2.0457x; 1.0627x over previous
#include <cuda_runtime.h>
#include <cuda_bf16.h>
#include <math.h>
#include <stdint.h>

#define VERY_NEG (-1e30f)

constexpr int Bz = 128;
constexpr int S  = 256;
constexpr int H  = 256;
constexpr int NH = 8;
constexpr int Dh = 32;
constexpr int C  = 20000;
constexpr int A  = 8;
constexpr int BS = Bz * S;
constexpr int CA = C * A;
constexpr int FF = 4 * H;
constexpr int NODES1 = 25001;
constexpr int QKVN = 3 * H;

// ---------------- scratch ------------------------------------------------------
__device__ uint32_t g_eh [(size_t)NODES1 * 128];
__device__ uint32_t g_el [(size_t)NODES1 * 128];
__device__ float    g_s  [CA];
__device__ float    g_dag[(size_t)C * H];
__device__ float    g_xv [(size_t)BS * H];
__device__ float    g_xd [(size_t)BS * H];
__device__ uint32_t g_xvh[(size_t)BS * 128], g_xvl[(size_t)BS * 128];
__device__ uint32_t g_xdh[(size_t)BS * 128], g_xdl[(size_t)BS * 128];
__device__ float    g_qkv[2][(size_t)BS * QKVN];
__device__ uint32_t g_cth[2][(size_t)BS * 128], g_ctl[2][(size_t)BS * 128];
__device__ float    g_t  [2][(size_t)BS * H];
__device__ uint32_t g_th [2][(size_t)BS * 128], g_tl [2][(size_t)BS * 128];
__device__ uint32_t g_fh [2][(size_t)BS * 512], g_fl [2][(size_t)BS * 512];
__device__ float    g_xdo[(size_t)BS * H];
// weight packs: [encoder][k-pair-major]
__device__ uint32_t g_wqkvh[2][128 * QKVN], g_wqkvl[2][128 * QKVN];
__device__ uint32_t g_woh [2][128 * 256],  g_wol [2][128 * 256];
__device__ uint32_t g_f1h [2][128 * 1024], g_f1l [2][128 * 1024];
__device__ uint32_t g_f2h [2][512 * 256],  g_f2l [2][512 * 256];
__device__ uint32_t g_w1h [256 * 256],  g_w1l [256 * 256];

// ---------------- helpers ------------------------------------------------------
__device__ __forceinline__ void mma_bf16(float* c, const uint32_t* a, const uint32_t* b) {
    asm volatile(
        "mma.sync.aligned.m16n8k16.row.col.f32.bf16.bf16.f32 "
        "{%0,%1,%2,%3}, {%4,%5,%6,%7}, {%8,%9}, {%0,%1,%2,%3};\n"
        : "+f"(c[0]), "+f"(c[1]), "+f"(c[2]), "+f"(c[3])
        : "r"(a[0]), "r"(a[1]), "r"(a[2]), "r"(a[3]),
          "r"(b[0]), "r"(b[1]));
}

__device__ __forceinline__ void split2(float x0, float x1, uint32_t& hi, uint32_t& lo) {
    __nv_bfloat16 h0 = __float2bfloat16_rn(x0);
    __nv_bfloat16 h1 = __float2bfloat16_rn(x1);
    __nv_bfloat16 l0 = __float2bfloat16_rn(x0 - __bfloat162float(h0));
    __nv_bfloat16 l1 = __float2bfloat16_rn(x1 - __bfloat162float(h1));
    hi = ((uint32_t)__bfloat16_as_ushort(h1) << 16) | __bfloat16_as_ushort(h0);
    lo = ((uint32_t)__bfloat16_as_ushort(l1) << 16) | __bfloat16_as_ushort(l0);
}

__global__ void pack_contig_kernel(const float* __restrict__ src, uint32_t* __restrict__ dh,
                                   uint32_t* __restrict__ dl, int n2)
{
    int idx = blockIdx.x * blockDim.x + threadIdx.x;
    if (idx >= n2) return;
    float2 v = ((const float2*)src)[idx];
    uint32_t h, l;
    split2(v.x, v.y, h, l);
    dh[idx] = h; dl[idx] = l;
}

// pack B [K][Nsrc] fp32 -> [K/2][Ndst] k-pair words at column offset
__global__ void pack_B_kernel(const float* __restrict__ src, uint32_t* __restrict__ dh,
                              uint32_t* __restrict__ dl, int Khalf, int Nsrc, int Ndst, int coff)
{
    int idx = blockIdx.x * blockDim.x + threadIdx.x;
    if (idx >= Khalf * Nsrc) return;
    int kp = idx / Nsrc, n = idx - kp * Nsrc;
    float a = src[(size_t)(2 * kp) * Nsrc + n];
    float b = src[(size_t)(2 * kp + 1) * Nsrc + n];
    uint32_t h, l;
    split2(a, b, h, l);
    dh[(size_t)kp * Ndst + coff + n] = h;
    dl[(size_t)kp * Ndst + coff + n] = l;
}

__global__ void s_init_kernel(float* __restrict__ s, const float* __restrict__ b2)
{
    int idx = blockIdx.x * blockDim.x + threadIdx.x;
    if (idx < CA) s[idx] = b2[0];
}

// ---------------- pointer-pair arg block (z selects encoder) -------------------
struct G2 {
    const uint32_t *Ah0, *Al0, *Bh0, *Bl0;
    const uint32_t *Ah1, *Al1, *Bh1, *Bl1;
    const float *bias0, *bias1, *Res0, *Res1;
    float *Cm0, *Cm1;
    uint32_t *Ch0, *Cl0, *Ch1, *Cl1;
};

// ---------------- split-bf16 tensor GEMM (pre-packed inputs) -------------------
template <bool RELU, bool BIAS, bool RES, bool GATHER, bool OUTF32, bool SPLIT, bool SCORE>
__global__ __launch_bounds__(256, 2)
void tgemm_kernel(G2 g, const float* __restrict__ w2, float* __restrict__ sout,
                  int M, int N, int K,
                  const int* __restrict__ gl, const int* __restrict__ ga)
{
    // A stride 12 -> conflict-free fragment LDS (12r+c bijective mod 32)
    __shared__ uint32_t As_h[2][128][12];
    __shared__ uint32_t As_l[2][128][12];
    __shared__ uint32_t Bs_h[2][8][136];
    __shared__ uint32_t Bs_l[2][8][136];

    const int z = blockIdx.z;
    const uint32_t* __restrict__ Ah = z ? g.Ah1 : g.Ah0;
    const uint32_t* __restrict__ Al = z ? g.Al1 : g.Al0;
    const uint32_t* __restrict__ Bh = z ? g.Bh1 : g.Bh0;
    const uint32_t* __restrict__ Bl = z ? g.Bl1 : g.Bl0;
    const float* __restrict__ bias  = z ? g.bias1 : g.bias0;
    const float* __restrict__ Res   = z ? g.Res1 : g.Res0;
    float* __restrict__ Cm          = z ? g.Cm1 : g.Cm0;
    uint32_t* __restrict__ Ch       = z ? g.Ch1 : g.Ch0;
    uint32_t* __restrict__ Cl       = z ? g.Cl1 : g.Cl0;

    const int tid  = threadIdx.x;
    const int lane = tid & 31;
    const int wid  = tid >> 5;
    const int warp_m = wid & 3;
    const int warp_n = wid >> 2;
    const int m0 = blockIdx.y * 128, n0 = blockIdx.x * 128;
    const int r = lane >> 2, c = lane & 3;
    const int Khalf = K >> 1;

    int arow[2], akp2[2], bkp[2], bcol2[2];
    #pragma unroll
    for (int i = 0; i < 2; i++) {
        int idx = tid + i * 256;
        arow[i] = idx >> 2;  akp2[i]  = (idx & 3) << 1;
        bkp[i]  = idx >> 6;  bcol2[i] = (idx & 63) << 1;
    }

    int grow_l[2], grow_a[2];
    if (GATHER) {
        #pragma unroll
        for (int i = 0; i < 2; i++) {
            grow_l[i] = gl[m0 + arow[i]];
            grow_a[i] = ga[m0 + arow[i]];
        }
    }

    float acc[2][8][4] = {};
    uint2 pah[2], pal[2], pbh[2], pbl[2];

    auto load_tile = [&](int k0) {
        const int kpb = k0 >> 1;
        #pragma unroll
        for (int i = 0; i < 2; i++) {
            size_t aaddr;
            if (GATHER) {
                const int kglob = k0 + akp2[i] * 2;
                const int src = (kglob < 256) ? grow_l[i] : grow_a[i];
                aaddr = (size_t)src * 128 + ((kpb + akp2[i]) & 127);
            } else {
                aaddr = (size_t)(m0 + arow[i]) * Khalf + kpb + akp2[i];
            }
            pah[i] = *(const uint2*)&Ah[aaddr];
            pal[i] = *(const uint2*)&Al[aaddr];
            const size_t baddr = (size_t)(kpb + bkp[i]) * N + n0 + bcol2[i];
            pbh[i] = *(const uint2*)&Bh[baddr];
            pbl[i] = *(const uint2*)&Bl[baddr];
        }
    };

    auto store_tile = [&](int buf) {
        #pragma unroll
        for (int i = 0; i < 2; i++) {
            *(uint2*)&As_h[buf][arow[i]][akp2[i]] = pah[i];
            *(uint2*)&As_l[buf][arow[i]][akp2[i]] = pal[i];
            *(uint2*)&Bs_h[buf][bkp[i]][bcol2[i]] = pbh[i];
            *(uint2*)&Bs_l[buf][bkp[i]][bcol2[i]] = pbl[i];
        }
    };

    load_tile(0);
    store_tile(0);
    __syncthreads();

    const int ntiles = K >> 4;
    for (int t = 0; t < ntiles; t++) {
        const int cur = t & 1;
        if (t + 1 < ntiles) load_tile((t + 1) << 4);

        uint32_t a_h[2][4], a_l[2][4], b_h[8][2], b_l[8][2];
        #pragma unroll
        for (int mt = 0; mt < 2; mt++) {
            const int row = warp_m * 32 + mt * 16 + r;
            a_h[mt][0] = As_h[cur][row][c];
            a_h[mt][1] = As_h[cur][row + 8][c];
            a_h[mt][2] = As_h[cur][row][c + 4];
            a_h[mt][3] = As_h[cur][row + 8][c + 4];
            a_l[mt][0] = As_l[cur][row][c];
            a_l[mt][1] = As_l[cur][row + 8][c];
            a_l[mt][2] = As_l[cur][row][c + 4];
            a_l[mt][3] = As_l[cur][row + 8][c + 4];
        }
        #pragma unroll
        for (int nt = 0; nt < 8; nt++) {
            const int col = warp_n * 64 + nt * 8 + r;
            b_h[nt][0] = Bs_h[cur][c][col];
            b_h[nt][1] = Bs_h[cur][c + 4][col];
            b_l[nt][0] = Bs_l[cur][c][col];
            b_l[nt][1] = Bs_l[cur][c + 4][col];
        }

        #pragma unroll
        for (int mt = 0; mt < 2; mt++)
            #pragma unroll
            for (int nt = 0; nt < 8; nt++) {
                mma_bf16(acc[mt][nt], a_h[mt], b_h[nt]);
                mma_bf16(acc[mt][nt], a_h[mt], b_l[nt]);
                mma_bf16(acc[mt][nt], a_l[mt], b_h[nt]);
            }

        if (t + 1 < ntiles) {
            store_tile(cur ^ 1);
            __syncthreads();
        }
    }

    float partial[4] = {0.f, 0.f, 0.f, 0.f};

    #pragma unroll
    for (int mt = 0; mt < 2; mt++) {
        #pragma unroll
        for (int nt = 0; nt < 8; nt++) {
            const int row0 = m0 + warp_m * 32 + mt * 16 + r;
            const int col  = n0 + warp_n * 64 + nt * 8 + 2 * c;
            #pragma unroll
            for (int h = 0; h < 2; h++) {
                float2 v = make_float2(acc[mt][nt][h * 2], acc[mt][nt][h * 2 + 1]);
                if (BIAS) {
                    const float2 bb = *(const float2*)&bias[col];
                    v.x += bb.x; v.y += bb.y;
                }
                if (RELU) { v.x = fmaxf(v.x, 0.f); v.y = fmaxf(v.y, 0.f); }
                const int row = row0 + h * 8;
                const size_t off = (size_t)row * N + col;
                if (RES) {
                    const float2 rr = *(const float2*)&Res[off];
                    v.x += rr.x; v.y += rr.y;
                }
                if (SCORE) {
                    const float2 ww = *(const float2*)&w2[col];
                    partial[mt * 2 + h] += v.x * ww.x + v.y * ww.y;
                }
                if (OUTF32) *(float2*)&Cm[off] = v;
                if (SPLIT) {
                    uint32_t hw, lw;
                    split2(v.x, v.y, hw, lw);
                    Ch[(size_t)row * (N >> 1) + (col >> 1)] = hw;
                    Cl[(size_t)row * (N >> 1) + (col >> 1)] = lw;
                }
            }
        }
    }

    if (SCORE) {
        #pragma unroll
        for (int mt = 0; mt < 2; mt++)
            #pragma unroll
            for (int h = 0; h < 2; h++) {
                float p = partial[mt * 2 + h];
                p += __shfl_xor_sync(0xffffffffu, p, 1);
                p += __shfl_xor_sync(0xffffffffu, p, 2);
                if ((lane & 3) == 0) {
                    const int row = m0 + warp_m * 32 + mt * 16 + r + h * 8;
                    atomicAdd(&sout[row], p);
                }
            }
    }
}

// ---------------- DAG softmax + weighted ancestor sum --------------------------
__global__ void dag_softmax_kernel(const float* __restrict__ s, const float* __restrict__ mask,
                                   const int* __restrict__ anc, const float* __restrict__ emb,
                                   float* __restrict__ dag)
{
    int gw = (blockIdx.x * blockDim.x + threadIdx.x) >> 5;
    int lane = threadIdx.x & 31;
    if (gw >= C) return;
    float sv = -3.0e38f;
    int av = 0;
    if (lane < 8) {
        float m = mask[gw * 8 + lane];
        sv = s[gw * 8 + lane] + (1.f - m) * VERY_NEG;
        av = anc[gw * 8 + lane];
    }
    float mx = sv;
    #pragma unroll
    for (int off = 4; off; off >>= 1) mx = fmaxf(mx, __shfl_xor_sync(0xffffffffu, mx, off));
    float e = (lane < 8) ? __expf(sv - mx) : 0.f;
    float su = e;
    #pragma unroll
    for (int off = 4; off; off >>= 1) su += __shfl_xor_sync(0xffffffffu, su, off);
    float wv = e / su;
    float w8[8];
    int   a8[8];
    #pragma unroll
    for (int a = 0; a < 8; a++) {
        w8[a] = __shfl_sync(0xffffffffu, wv, a);
        a8[a] = __shfl_sync(0xffffffffu, av, a);
    }
    const float4* e4 = (const float4*)emb;
    #pragma unroll
    for (int rep = 0; rep < 2; rep++) {
        int f4i = lane + rep * 32;
        float4 acc = make_float4(0.f, 0.f, 0.f, 0.f);
        #pragma unroll
        for (int a = 0; a < 8; a++) {
            float4 v = e4[(size_t)a8[a] * 64 + f4i];
            acc.x = fmaf(w8[a], v.x, acc.x);
            acc.y = fmaf(w8[a], v.y, acc.y);
            acc.z = fmaf(w8[a], v.z, acc.z);
            acc.w = fmaf(w8[a], v.w, acc.w);
        }
        ((float4*)dag)[(size_t)gw * 64 + f4i] = acc;
    }
}

__global__ void embed_gather_kernel(const int* __restrict__ ids, const float* __restrict__ embw,
                                    const float* __restrict__ dag,
                                    float* __restrict__ xv, float* __restrict__ xd,
                                    uint32_t* __restrict__ xvh, uint32_t* __restrict__ xvl,
                                    uint32_t* __restrict__ xdh, uint32_t* __restrict__ xdl)
{
    int idx = blockIdx.x * blockDim.x + threadIdx.x;
    if (idx >= BS * 64) return;
    int bs = idx >> 6, h4 = idx & 63;
    int id = ids[bs];
    float4 vv = ((const float4*)embw)[(size_t)id * 64 + h4];
    ((float4*)xv)[(size_t)bs * 64 + h4] = vv;
    float4 dv = make_float4(0.f, 0.f, 0.f, 0.f);
    if (id > 0) dv = ((const float4*)dag)[(size_t)(id - 1) * 64 + h4];
    ((float4*)xd)[(size_t)bs * 64 + h4] = dv;

    uint32_t h0, l0, h1, l1;
    split2(vv.x, vv.y, h0, l0);
    split2(vv.z, vv.w, h1, l1);
    xvh[(size_t)bs * 128 + h4 * 2]     = h0;
    xvh[(size_t)bs * 128 + h4 * 2 + 1] = h1;
    xvl[(size_t)bs * 128 + h4 * 2]     = l0;
    xvl[(size_t)bs * 128 + h4 * 2 + 1] = l1;
    split2(dv.x, dv.y, h0, l0);
    split2(dv.z, dv.w, h1, l1);
    xdh[(size_t)bs * 128 + h4 * 2]     = h0;
    xdh[(size_t)bs * 128 + h4 * 2 + 1] = h1;
    xdl[(size_t)bs * 128 + h4 * 2]     = l0;
    xdl[(size_t)bs * 128 + h4 * 2 + 1] = l1;
}

// ---------------- attention (z selects encoder) --------------------------------
struct A2 {
    const float *qkv0, *qkv1;
    uint32_t *h0, *l0, *h1, *l1;
};

__global__ void attention_kernel(A2 g, const float* __restrict__ cmask)
{
    extern __shared__ float sm[];
    float* Ks = sm;
    float* Vs = sm + S * Dh;
    float* madd = Vs + S * Dh;
    const int h = blockIdx.x, b = blockIdx.y, z = blockIdx.z;
    const float* __restrict__ QKV = z ? g.qkv1 : g.qkv0;
    uint32_t* __restrict__ cth = z ? g.h1 : g.h0;
    uint32_t* __restrict__ ctl = z ? g.l1 : g.l0;
    const int tid = threadIdx.x;
    const size_t rowbase = (size_t)b * S * QKVN;
    const int qo = h * Dh, ko = H + h * Dh, vo = 2 * H + h * Dh;

    for (int i = tid; i < S * 8; i += 256) {
        int row = i >> 3, slot = (i & 7) << 2;
        *(float4*)&Ks[row * Dh + slot] = *(const float4*)&QKV[rowbase + (size_t)row * QKVN + ko + slot];
        *(float4*)&Vs[row * Dh + slot] = *(const float4*)&QKV[rowbase + (size_t)row * QKVN + vo + slot];
    }
    madd[tid] = (1.0f - cmask[b * S + tid]) * VERY_NEG;
    __syncthreads();

    float q[32];
    const float* qp = &QKV[rowbase + (size_t)tid * QKVN + qo];
    #pragma unroll
    for (int i = 0; i < 32; i += 4) {
        float4 t = *(const float4*)&qp[i];
        q[i] = t.x; q[i + 1] = t.y; q[i + 2] = t.z; q[i + 3] = t.w;
    }
    const float scale = rsqrtf(32.0f);
    float m = -INFINITY, l = 0.f, o[32];
    #pragma unroll
    for (int i = 0; i < 32; i++) o[i] = 0.f;

    for (int k0 = 0; k0 < S; k0 += 16) {
        float sc[16];
        float cm = -INFINITY;
        #pragma unroll
        for (int kk = 0; kk < 16; kk++) {
            const float* kr = &Ks[(k0 + kk) * Dh];
            float d = 0.f;
            #pragma unroll
            for (int i = 0; i < 32; i++) d = fmaf(q[i], kr[i], d);
            sc[kk] = d * scale + madd[k0 + kk];
            cm = fmaxf(cm, sc[kk]);
        }
        const float mn = fmaxf(m, cm);
        const float corr = __expf(m - mn);
        l *= corr;
        #pragma unroll
        for (int i = 0; i < 32; i++) o[i] *= corr;
        #pragma unroll
        for (int kk = 0; kk < 16; kk++) {
            const float p = __expf(sc[kk] - mn);
            l += p;
            const float* vr = &Vs[(k0 + kk) * Dh];
            #pragma unroll
            for (int i = 0; i < 32; i++) o[i] = fmaf(p, vr[i], o[i]);
        }
        m = mn;
    }
    const float inv = 1.0f / l;
    const size_t prow = (size_t)(b * S + tid) * 128 + h * 16;
    #pragma unroll
    for (int i = 0; i < 32; i += 2) {
        uint32_t hw, lw;
        split2(o[i] * inv, o[i + 1] * inv, hw, lw);
        cth[prow + i / 2] = hw;
        ctl[prow + i / 2] = lw;
    }
}

// ---------------- pooling ------------------------------------------------------
__global__ void pool_kernel(const float* __restrict__ x, const float* __restrict__ cmask,
                            const float* __restrict__ pw, const float* __restrict__ pb,
                            float* __restrict__ out)
{
    __shared__ float spw[H];
    __shared__ float sc[S];
    __shared__ float red[8];
    const int b = blockIdx.x, tid = threadIdx.x;
    const int lane = tid & 31, w = tid >> 5;
    spw[tid] = pw[tid];
    __syncthreads();

    for (int row = w; row < S; row += 8) {
        const float* xp = &x[((size_t)b * S + row) * H];
        float4 a0 = *(const float4*)&xp[lane * 4];
        float4 a1 = *(const float4*)&xp[128 + lane * 4];
        float acc = a0.x * spw[lane * 4 + 0] + a0.y * spw[lane * 4 + 1]
                  + a0.z * spw[lane * 4 + 2] + a0.w * spw[lane * 4 + 3]
                  + a1.x * spw[128 + lane * 4 + 0] + a1.y * spw[128 + lane * 4 + 1]
                  + a1.z * spw[128 + lane * 4 + 2] + a1.w * spw[128 + lane * 4 + 3];
        #pragma unroll
        for (int off = 16; off; off >>= 1) acc += __shfl_xor_sync(0xffffffffu, acc, off);
        if (lane == 0)
            sc[row] = acc + pb[0] + (1.f - cmask[b * S + row]) * VERY_NEG;
    }
    __syncthreads();

    float v = sc[tid];
    float mx = v;
    #pragma unroll
    for (int off = 16; off; off >>= 1) mx = fmaxf(mx, __shfl_xor_sync(0xffffffffu, mx, off));
    if (lane == 0) red[w] = mx;
    __syncthreads();
    float bm = red[0];
    #pragma unroll
    for (int i = 1; i < 8; i++) bm = fmaxf(bm, red[i]);
    __syncthreads();
    float e = __expf(v - bm);
    float su = e;
    #pragma unroll
    for (int off = 16; off; off >>= 1) su += __shfl_xor_sync(0xffffffffu, su, off);
    if (lane == 0) red[w] = su;
    __syncthreads();
    float tot = 0.f;
    #pragma unroll
    for (int i = 0; i < 8; i++) tot += red[i];
    sc[tid] = e / tot;
    __syncthreads();

    float acc = 0.f;
    for (int ss = 0; ss < S; ss++)
        acc = fmaf(sc[ss], x[((size_t)b * S + ss) * H + tid], acc);
    out[(size_t)b * H + tid] = acc;
}

// ---------------- host ----------------------------------------------------------
extern "C" void kernel_launch(void* const* d_in, const int* in_sizes, int n_in,
                              void* d_out, int out_size)
{
    const int*   input_ids   = (const int*)d_in[0];
    const float* code_mask   = (const float*)d_in[1];
    const int*   dx_leaves   = (const int*)d_in[2];
    const int*   dx_anc      = (const int*)d_in[3];
    const float* dx_mask     = (const float*)d_in[4];
    const float* embed_init  = (const float*)d_in[5];
    const float* embed_inp   = (const float*)d_in[6];
    const float* attn_w1     = (const float*)d_in[7];
    const float* attn_b1     = (const float*)d_in[8];
    const float* attn_w2     = (const float*)d_in[9];
    const float* attn_b2     = (const float*)d_in[10];
    const float* pool_w      = (const float*)d_in[11];
    const float* pool_b      = (const float*)d_in[12];
    const float* enc_w[2][8];   // [z][wq,wk,wv,wo,fw1,fb1,fw2,fb2]
    for (int z = 0; z < 2; z++)
        for (int j = 0; j < 8; j++)
            enc_w[z][j] = (const float*)d_in[13 + z * 8 + j];
    float* out = (float*)d_out;

    uint32_t *eh, *el, *xvh, *xvl, *xdh, *xdl, *w1h, *w1l;
    uint32_t *cth[2], *ctl[2], *th[2], *tl[2], *fh[2], *fl[2];
    uint32_t *wqkvh[2], *wqkvl[2], *woh[2], *wol[2], *f1h[2], *f1l[2], *f2h[2], *f2l[2];
    float *s, *dag, *xv, *xd, *xdo, *qkv[2], *t[2];
    {
        char* p;
        cudaGetSymbolAddress((void**)&eh, g_eh);   cudaGetSymbolAddress((void**)&el, g_el);
        cudaGetSymbolAddress((void**)&s, g_s);     cudaGetSymbolAddress((void**)&dag, g_dag);
        cudaGetSymbolAddress((void**)&xv, g_xv);   cudaGetSymbolAddress((void**)&xd, g_xd);
        cudaGetSymbolAddress((void**)&xvh, g_xvh); cudaGetSymbolAddress((void**)&xvl, g_xvl);
        cudaGetSymbolAddress((void**)&xdh, g_xdh); cudaGetSymbolAddress((void**)&xdl, g_xdl);
        cudaGetSymbolAddress((void**)&xdo, g_xdo);
        cudaGetSymbolAddress((void**)&w1h, g_w1h); cudaGetSymbolAddress((void**)&w1l, g_w1l);
        cudaGetSymbolAddress((void**)&p, g_qkv);   qkv[0] = (float*)p;    qkv[1] = qkv[0] + (size_t)BS * QKVN;
        cudaGetSymbolAddress((void**)&p, g_t);     t[0] = (float*)p;      t[1] = t[0] + (size_t)BS * H;
        cudaGetSymbolAddress((void**)&p, g_cth);   cth[0] = (uint32_t*)p; cth[1] = cth[0] + (size_t)BS * 128;
        cudaGetSymbolAddress((void**)&p, g_ctl);   ctl[0] = (uint32_t*)p; ctl[1] = ctl[0] + (size_t)BS * 128;
        cudaGetSymbolAddress((void**)&p, g_th);    th[0] = (uint32_t*)p;  th[1] = th[0] + (size_t)BS * 128;
        cudaGetSymbolAddress((void**)&p, g_tl);    tl[0] = (uint32_t*)p;  tl[1] = tl[0] + (size_t)BS * 128;
        cudaGetSymbolAddress((void**)&p, g_fh);    fh[0] = (uint32_t*)p;  fh[1] = fh[0] + (size_t)BS * 512;
        cudaGetSymbolAddress((void**)&p, g_fl);    fl[0] = (uint32_t*)p;  fl[1] = fl[0] + (size_t)BS * 512;
        cudaGetSymbolAddress((void**)&p, g_wqkvh); wqkvh[0] = (uint32_t*)p; wqkvh[1] = wqkvh[0] + 128 * QKVN;
        cudaGetSymbolAddress((void**)&p, g_wqkvl); wqkvl[0] = (uint32_t*)p; wqkvl[1] = wqkvl[0] + 128 * QKVN;
        cudaGetSymbolAddress((void**)&p, g_woh);   woh[0] = (uint32_t*)p;   woh[1] = woh[0] + 128 * 256;
        cudaGetSymbolAddress((void**)&p, g_wol);   wol[0] = (uint32_t*)p;   wol[1] = wol[0] + 128 * 256;
        cudaGetSymbolAddress((void**)&p, g_f1h);   f1h[0] = (uint32_t*)p;   f1h[1] = f1h[0] + 128 * 1024;
        cudaGetSymbolAddress((void**)&p, g_f1l);   f1l[0] = (uint32_t*)p;   f1l[1] = f1l[0] + 128 * 1024;
        cudaGetSymbolAddress((void**)&p, g_f2h);   f2h[0] = (uint32_t*)p;   f2h[1] = f2h[0] + 512 * 256;
        cudaGetSymbolAddress((void**)&p, g_f2l);   f2l[0] = (uint32_t*)p;   f2l[1] = f2l[0] + 512 * 256;
    }

    const int asmem = (2 * S * Dh + S) * (int)sizeof(float);
    cudaFuncSetAttribute(attention_kernel, cudaFuncAttributeMaxDynamicSharedMemorySize, asmem);

    const int PT = 256;
    // packing: emb, dag w1, all encoder weights
    pack_contig_kernel<<<(NODES1 * 128 + PT - 1) / PT, PT>>>(embed_init, eh, el, NODES1 * 128);
    pack_B_kernel<<<(256 * 256 + PT - 1) / PT, PT>>>(attn_w1, w1h, w1l, 256, 256, 256, 0);
    s_init_kernel<<<(CA + PT - 1) / PT, PT>>>(s, attn_b2);
    for (int z = 0; z < 2; z++) {
        pack_B_kernel<<<(128 * 256 + PT - 1) / PT, PT>>>(enc_w[z][0], wqkvh[z], wqkvl[z], 128, 256, QKVN, 0);
        pack_B_kernel<<<(128 * 256 + PT - 1) / PT, PT>>>(enc_w[z][1], wqkvh[z], wqkvl[z], 128, 256, QKVN, 256);
        pack_B_kernel<<<(128 * 256 + PT - 1) / PT, PT>>>(enc_w[z][2], wqkvh[z], wqkvl[z], 128, 256, QKVN, 512);
        pack_B_kernel<<<(128 * 256 + PT - 1) / PT, PT>>>(enc_w[z][3], woh[z], wol[z], 128, 256, 256, 0);
        pack_B_kernel<<<(128 * 1024 + PT - 1) / PT, PT>>>(enc_w[z][4], f1h[z], f1l[z], 128, 1024, 1024, 0);
        pack_B_kernel<<<(512 * 256 + PT - 1) / PT, PT>>>(enc_w[z][6], f2h[z], f2l[z], 512, 256, 256, 0);
    }

    // DAG MLP: gathered A + fused score (z duplicated; grid z=1)
    {
        G2 g{};
        g.Ah0 = g.Ah1 = eh;  g.Al0 = g.Al1 = el;
        g.Bh0 = g.Bh1 = w1h; g.Bl0 = g.Bl1 = w1l;
        g.bias0 = g.bias1 = attn_b1;
        tgemm_kernel<true, true, false, true, false, false, true><<<dim3(2, CA / 128, 1), 256>>>(
            g, attn_w2, s, CA, 256, 512, dx_leaves, dx_anc);
    }
    dag_softmax_kernel<<<C / 8, 256>>>(s, dx_mask, dx_anc, embed_init, dag);
    embed_gather_kernel<<<(BS * 64 + PT - 1) / PT, PT>>>(input_ids, embed_inp, dag,
                                                         xv, xd, xvh, xvl, xdh, xdl);

    // --- both encoders batched over gridDim.z ---
    // QKV
    {
        G2 g{};
        g.Ah0 = xvh; g.Al0 = xvl; g.Ah1 = xdh; g.Al1 = xdl;
        g.Bh0 = wqkvh[0]; g.Bl0 = wqkvl[0]; g.Bh1 = wqkvh[1]; g.Bl1 = wqkvl[1];
        g.Cm0 = qkv[0]; g.Cm1 = qkv[1];
        tgemm_kernel<false, false, false, false, true, false, false><<<dim3(QKVN / 128, BS / 128, 2), 256>>>(
            g, nullptr, nullptr, BS, QKVN, H, nullptr, nullptr);
    }
    {
        A2 a{qkv[0], qkv[1], cth[0], ctl[0], cth[1], ctl[1]};
        attention_kernel<<<dim3(NH, Bz, 2), 256, asmem>>>(a, code_mask);
    }
    // wo + residual -> t (fp32 + packed)
    {
        G2 g{};
        g.Ah0 = cth[0]; g.Al0 = ctl[0]; g.Ah1 = cth[1]; g.Al1 = ctl[1];
        g.Bh0 = woh[0]; g.Bl0 = wol[0]; g.Bh1 = woh[1]; g.Bl1 = wol[1];
        g.Res0 = xv; g.Res1 = xd;
        g.Cm0 = t[0]; g.Cm1 = t[1];
        g.Ch0 = th[0]; g.Cl0 = tl[0]; g.Ch1 = th[1]; g.Cl1 = tl[1];
        tgemm_kernel<false, false, true, false, true, true, false><<<dim3(2, BS / 128, 2), 256>>>(
            g, nullptr, nullptr, BS, H, H, nullptr, nullptr);
    }
    // ffn1 -> packed f
    {
        G2 g{};
        g.Ah0 = th[0]; g.Al0 = tl[0]; g.Ah1 = th[1]; g.Al1 = tl[1];
        g.Bh0 = f1h[0]; g.Bl0 = f1l[0]; g.Bh1 = f1h[1]; g.Bl1 = f1l[1];
        g.bias0 = enc_w[0][5]; g.bias1 = enc_w[1][5];
        g.Ch0 = fh[0]; g.Cl0 = fl[0]; g.Ch1 = fh[1]; g.Cl1 = fl[1];
        tgemm_kernel<true, true, false, false, false, true, false><<<dim3(FF / 128, BS / 128, 2), 256>>>(
            g, nullptr, nullptr, BS, FF, H, nullptr, nullptr);
    }
    // ffn2 + residual -> outputs
    {
        G2 g{};
        g.Ah0 = fh[0]; g.Al0 = fl[0]; g.Ah1 = fh[1]; g.Al1 = fl[1];
        g.Bh0 = f2h[0]; g.Bl0 = f2l[0]; g.Bh1 = f2h[1]; g.Bl1 = f2l[1];
        g.bias0 = enc_w[0][7]; g.bias1 = enc_w[1][7];
        g.Res0 = t[0]; g.Res1 = t[1];
        g.Cm0 = out; g.Cm1 = xdo;
        tgemm_kernel<false, true, true, false, true, false, false><<<dim3(2, BS / 128, 2), 256>>>(
            g, nullptr, nullptr, BS, H, FF, nullptr, nullptr);
    }

    pool_kernel<<<Bz, 256>>>(xdo, code_mask, pool_w, pool_b, out + (size_t)BS * H);
}